// round 14
// baseline (speedup 1.0000x reference)
#include <cuda_runtime.h>
#include <cuda_fp16.h>
#include <math.h>

// Problem constants
#define NB   4
#define LEN  5440
#define NTOK (NB * LEN)          // 21760
#define CCH  256
#define NH   8
#define DH   32
#define NL   4
#define NP   4
#define DFF  1024
#define LN_EPS 1e-5f

// Padded value layout: per level pad 2 on all sides, fp16.
#define PBATCH 6464
#define PB0 0
#define PB1 4624
#define PB2 5920
#define PB3 6320

// ---------------------------------------------------------------------------
// Scratch
// ---------------------------------------------------------------------------
__device__ __half g_q1   [NTOK * CCH];
__device__ __half g_src1 [NTOK * CCH];
__device__ __half g_msda1[NTOK * CCH];
__device__ __half g_x1   [NTOK * CCH];
__device__ __half g_h1   [NTOK * DFF];
__device__ __half g_valp [NB * PBATCH * CCH];

__device__ float g_off [NTOK * CCH];
__device__ float g_aw  [NTOK * 128];
__device__ float g_x   [NTOK * CCH];

__device__ __half g_woffh [CCH * CCH];
__device__ __half g_wattnh[128 * CCH];
__device__ __half g_wvalh [CCH * CCH];
__device__ __half g_wouth [CCH * CCH];
__device__ __half g_w1h   [DFF * CCH];
__device__ __half g_w2h   [CCH * DFF];

// ---------------------------------------------------------------------------
// helpers
// ---------------------------------------------------------------------------
__device__ __forceinline__ unsigned smem_u32(const void* p) {
    unsigned a;
    asm("{ .reg .u64 t; cvta.to.shared.u64 t, %1; cvt.u32.u64 %0, t; }" : "=r"(a) : "l"(p));
    return a;
}

__device__ __forceinline__ void cp_async16(unsigned dst, const void* src) {
    asm volatile("cp.async.cg.shared.global [%0], [%1], 16;\n" :: "r"(dst), "l"(src));
}
__device__ __forceinline__ void cp_commit() {
    asm volatile("cp.async.commit_group;\n" ::: "memory");
}
template<int N>
__device__ __forceinline__ void cp_wait() {
    asm volatile("cp.async.wait_group %0;\n" :: "n"(N) : "memory");
}

__device__ __forceinline__ void ldm4(unsigned& r0, unsigned& r1, unsigned& r2, unsigned& r3,
                                     unsigned a) {
    asm volatile("ldmatrix.sync.aligned.m8n8.x4.shared.b16 {%0,%1,%2,%3}, [%4];"
                 : "=r"(r0), "=r"(r1), "=r"(r2), "=r"(r3) : "r"(a));
}

__device__ __forceinline__ void mma_f16(float c[4],
                                        unsigned a0, unsigned a1, unsigned a2, unsigned a3,
                                        unsigned b0, unsigned b1) {
    asm volatile(
        "mma.sync.aligned.m16n8k16.row.col.f32.f16.f16.f32 "
        "{%0,%1,%2,%3},{%4,%5,%6,%7},{%8,%9},{%0,%1,%2,%3};"
        : "+f"(c[0]), "+f"(c[1]), "+f"(c[2]), "+f"(c[3])
        : "r"(a0), "r"(a1), "r"(a2), "r"(a3), "r"(b0), "r"(b1));
}

// token -> padded value row base (channel 0)
__device__ __forceinline__ __half* valp_row(__half* Vp, int t) {
    int b = t / LEN;
    int pos = t - b * LEN;
    int base, W4, ys, m, loc;
    if (pos < 4096)      { loc = pos;        base = PB0; W4 = 68; ys = 6; m = 63; }
    else if (pos < 5120) { loc = pos - 4096; base = PB1; W4 = 36; ys = 5; m = 31; }
    else if (pos < 5376) { loc = pos - 5120; base = PB2; W4 = 20; ys = 4; m = 15; }
    else                 { loc = pos - 5376; base = PB3; W4 = 12; ys = 3; m = 7; }
    int y = loc >> ys, x = loc & m;
    return Vp + ((size_t)b * PBATCH + base + (y + 2) * W4 + (x + 2)) * CCH;
}

// ---------------------------------------------------------------------------
// Generic GEMM: BM=64, BN=128, NST=4, 2 CTAs/SM.
// OUT_MODE 0: fp32 out. 1: relu + fp16 out. 2: fp16 into padded value layout.
// ---------------------------------------------------------------------------
#define NST 4
#define GBM 64
#define A_BYTES (GBM * 128)
#define STAGE_SZ ((GBM + 128) * 128)   // 24576

__device__ __forceinline__ void gemm_load_stage(unsigned sb, int stage,
                                                const __half* A, const __half* B,
                                                int K, int kt, int tid) {
    const unsigned abase = sb + stage * STAGE_SZ;
    const unsigned bbase = abase + A_BYTES;
    const __half* ag = A + kt * 64;
    const __half* bg = B + kt * 64;
    #pragma unroll
    for (int i = 0; i < 2; i++) {
        int id = tid + i * 256;
        int r = id >> 3, c = id & 7;
        unsigned off = (unsigned)(r * 128 + ((c ^ (r & 7)) << 4));
        cp_async16(abase + off, ag + (size_t)r * K + c * 8);
    }
    #pragma unroll
    for (int i = 0; i < 4; i++) {
        int id = tid + i * 256;
        int r = id >> 3, c = id & 7;
        unsigned off = (unsigned)(r * 128 + ((c ^ (r & 7)) << 4));
        cp_async16(bbase + off, bg + (size_t)r * K + c * 8);
    }
    cp_commit();
}

template<int OUT_MODE>
__device__ __forceinline__ void gemm_body(const __half* A, const __half* B,
                                          const float* bias, float* Cf, __half* C2,
                                          int N, int K, int row_base, int col_base,
                                          char* smem) {
    const unsigned sb = smem_u32(smem);
    const int tid = threadIdx.x;
    const int warp = tid >> 5, lane = tid & 31;
    const int wm = warp & 1, wn = warp >> 1;
    const int KT = K >> 6;

    float acc[2][4][4];
    #pragma unroll
    for (int i = 0; i < 2; i++)
        #pragma unroll
        for (int j = 0; j < 4; j++)
            #pragma unroll
            for (int r = 0; r < 4; r++) acc[i][j][r] = 0.f;

    #pragma unroll
    for (int s = 0; s < NST - 1; s++) {
        if (s < KT) gemm_load_stage(sb, s, A, B, K, s, tid);
        else        cp_commit();
    }

    const int a_row  = (lane & 15);
    const int a_csel = (lane >> 4);
    const int b_rsel = ((lane >> 4) << 3) + (lane & 7);
    const int b_csel = ((lane >> 3) & 1);

    for (int kt = 0; kt < KT; kt++) {
        const int stage = kt % NST;
        cp_wait<NST - 2>();
        __syncthreads();
        if (kt + NST - 1 < KT)
            gemm_load_stage(sb, (kt + NST - 1) % NST, A, B, K, kt + NST - 1, tid);
        else
            cp_commit();

        const unsigned ab = sb + stage * STAGE_SZ;
        const unsigned bb = ab + A_BYTES;

        #pragma unroll
        for (int kk = 0; kk < 4; kk++) {
            const int c = kk * 2;
            unsigned af[2][4], bf[2][4];
            #pragma unroll
            for (int mi = 0; mi < 2; mi++) {
                int row = wm * 32 + mi * 16 + a_row;
                unsigned so = (unsigned)(row * 128 + (((c + a_csel) ^ (row & 7)) << 4));
                ldm4(af[mi][0], af[mi][1], af[mi][2], af[mi][3], ab + so);
            }
            #pragma unroll
            for (int nj2 = 0; nj2 < 2; nj2++) {
                int nrow = wn * 32 + nj2 * 16 + b_rsel;
                unsigned so = (unsigned)(nrow * 128 + (((c + b_csel) ^ (nrow & 7)) << 4));
                ldm4(bf[nj2][0], bf[nj2][1], bf[nj2][2], bf[nj2][3], bb + so);
            }
            #pragma unroll
            for (int mi = 0; mi < 2; mi++)
                #pragma unroll
                for (int nj = 0; nj < 4; nj++) {
                    const unsigned* b = bf[nj >> 1];
                    unsigned b0 = (nj & 1) ? b[2] : b[0];
                    unsigned b1 = (nj & 1) ? b[3] : b[1];
                    mma_f16(acc[mi][nj], af[mi][0], af[mi][1], af[mi][2], af[mi][3], b0, b1);
                }
        }
    }

    const int col0 = wn * 32 + (lane & 3) * 2;
    #pragma unroll
    for (int mi = 0; mi < 2; mi++) {
        int row = row_base + wm * 32 + mi * 16 + (lane >> 2);
        __half *p0 = nullptr, *p1 = nullptr;
        if (OUT_MODE == 2) {
            p0 = valp_row(C2, row) + col_base;
            p1 = valp_row(C2, row + 8) + col_base;
        }
        #pragma unroll
        for (int nj = 0; nj < 4; nj++) {
            int col = col0 + nj * 8;
            float b0v = bias[col], b1v = bias[col + 1];
            float v00 = acc[mi][nj][0] + b0v, v01 = acc[mi][nj][1] + b1v;
            float v10 = acc[mi][nj][2] + b0v, v11 = acc[mi][nj][3] + b1v;
            if (OUT_MODE == 0) {
                *(float2*)(Cf + (size_t)row * N + col)       = make_float2(v00, v01);
                *(float2*)(Cf + (size_t)(row + 8) * N + col) = make_float2(v10, v11);
            } else if (OUT_MODE == 1) {
                v00 = fmaxf(v00, 0.f); v01 = fmaxf(v01, 0.f);
                v10 = fmaxf(v10, 0.f); v11 = fmaxf(v11, 0.f);
                *(__half2*)(C2 + (size_t)row * N + col)       = __floats2half2_rn(v00, v01);
                *(__half2*)(C2 + (size_t)(row + 8) * N + col) = __floats2half2_rn(v10, v11);
            } else {
                *(__half2*)(p0 + col) = __floats2half2_rn(v00, v01);
                *(__half2*)(p1 + col) = __floats2half2_rn(v10, v11);
            }
        }
    }
}

template<int OUT_MODE>
__global__ __launch_bounds__(256, 2)
void mma_gemm(const __half* __restrict__ A, const __half* __restrict__ Bt,
              const float* __restrict__ bias, float* __restrict__ Cf,
              __half* __restrict__ C2, int N, int K) {
    extern __shared__ __align__(1024) char smem[];
    const int bx = blockIdx.x, by = blockIdx.y;
    gemm_body<OUT_MODE>(A + (size_t)by * GBM * K,
                        Bt + (size_t)bx * 128 * (size_t)K,
                        bias + bx * 128,
                        Cf ? Cf + bx * 128 : nullptr,
                        C2 ? C2 + bx * 128 : nullptr,
                        N, K, by * GBM, 0, smem);
}

// fused projection GEMM: bx selects {off0, off1, logits, val0, val1}
__global__ __launch_bounds__(256, 2)
void proj_gemm(const __half* __restrict__ q1, const __half* __restrict__ src1,
               const __half* __restrict__ woffh, const __half* __restrict__ wattnh,
               const __half* __restrict__ wvalh,
               const float* __restrict__ b_off, const float* __restrict__ b_attn,
               const float* __restrict__ b_val,
               float* __restrict__ c_off, float* __restrict__ c_aw,
               __half* __restrict__ valp) {
    extern __shared__ __align__(1024) char smem[];
    const int bx = blockIdx.x, by = blockIdx.y;
    const int K = CCH;

    if (bx < 2) {
        gemm_body<0>(q1 + (size_t)by * GBM * K, woffh + (size_t)bx * 128 * K,
                     b_off + bx * 128, c_off + bx * 128, nullptr,
                     CCH, K, by * GBM, 0, smem);
    } else if (bx == 2) {
        gemm_body<0>(q1 + (size_t)by * GBM * K, wattnh,
                     b_attn, c_aw, nullptr,
                     128, K, by * GBM, 0, smem);
    } else {
        int s = bx - 3;
        gemm_body<2>(src1 + (size_t)by * GBM * K, wvalh + (size_t)s * 128 * K,
                     b_val + s * 128, nullptr, valp,
                     CCH, K, by * GBM, s * 128, smem);
    }
}

// ---------------------------------------------------------------------------
// Fused GEMM(BM=32, BN=256) + residual + LayerNorm.
// WRITE_HALF 1: also write fp16 copy of the LN output (for attn+LN1 -> x1).
// A [M][K] fp16, Bt [256][K] fp16. resid fp32. 2-stage, 2 CTAs/SM.
// ---------------------------------------------------------------------------
#define ALN_STAGE ((32 + 256) * 128)        // 36864
#define ALN_CSTR 264
#define ALN_SMEM (2 * ALN_STAGE + 32 * ALN_CSTR * 4)   // 107520

template<int WRITE_HALF>
__global__ __launch_bounds__(256, 2)
void gemm_ln(const __half* __restrict__ A, const __half* __restrict__ Bt,
             const float* __restrict__ bias, const float* __restrict__ resid,
             const float* __restrict__ g, const float* __restrict__ be,
             float* __restrict__ xout, __half* __restrict__ x1out, int K) {
    extern __shared__ __align__(1024) char smem[];
    const unsigned sb = smem_u32(smem);
    float* cbuf = (float*)(smem + 2 * ALN_STAGE);
    const int tid = threadIdx.x;
    const int warp = tid >> 5, lane = tid & 31;
    const int row0 = blockIdx.x * 32;
    const int KT = K >> 6;

    float acc[2][4][4];
    #pragma unroll
    for (int i = 0; i < 2; i++)
        #pragma unroll
        for (int j = 0; j < 4; j++)
            #pragma unroll
            for (int r = 0; r < 4; r++) acc[i][j][r] = 0.f;

    // stage 0
    {
        const unsigned abase = sb;
        const unsigned bbase = sb + 32 * 128;
        const __half* ag = A + (size_t)row0 * K;
        {
            int r = tid >> 3, c = tid & 7;
            unsigned off = (unsigned)(r * 128 + ((c ^ (r & 7)) << 4));
            cp_async16(abase + off, ag + (size_t)r * K + c * 8);
        }
        #pragma unroll
        for (int i = 0; i < 8; i++) {
            int id = tid + i * 256;
            int r = id >> 3, c = id & 7;
            unsigned off = (unsigned)(r * 128 + ((c ^ (r & 7)) << 4));
            cp_async16(bbase + off, Bt + (size_t)r * K + c * 8);
        }
        cp_commit();
    }

    const int a_row  = (lane & 15);
    const int a_csel = (lane >> 4);
    const int b_rsel = ((lane >> 4) << 3) + (lane & 7);
    const int b_csel = ((lane >> 3) & 1);

    for (int kt = 0; kt < KT; kt++) {
        const int stage = kt & 1;
        cp_wait<0>();
        __syncthreads();
        if (kt + 1 < KT) {
            const unsigned abase = sb + (stage ^ 1) * ALN_STAGE;
            const unsigned bbase = abase + 32 * 128;
            const __half* ag = A + (size_t)row0 * K + (kt + 1) * 64;
            const __half* bg = Bt + (kt + 1) * 64;
            {
                int r = tid >> 3, c = tid & 7;
                unsigned off = (unsigned)(r * 128 + ((c ^ (r & 7)) << 4));
                cp_async16(abase + off, ag + (size_t)r * K + c * 8);
            }
            #pragma unroll
            for (int i = 0; i < 8; i++) {
                int id = tid + i * 256;
                int r = id >> 3, c = id & 7;
                unsigned off = (unsigned)(r * 128 + ((c ^ (r & 7)) << 4));
                cp_async16(bbase + off, bg + (size_t)r * K + c * 8);
            }
            cp_commit();
        }

        const unsigned ab = sb + stage * ALN_STAGE;
        const unsigned bb = ab + 32 * 128;

        #pragma unroll
        for (int kk = 0; kk < 4; kk++) {
            const int c = kk * 2;
            unsigned af[2][4], bf[2][4];
            #pragma unroll
            for (int mi = 0; mi < 2; mi++) {
                int row = mi * 16 + a_row;
                unsigned so = (unsigned)(row * 128 + (((c + a_csel) ^ (row & 7)) << 4));
                ldm4(af[mi][0], af[mi][1], af[mi][2], af[mi][3], ab + so);
            }
            #pragma unroll
            for (int nj2 = 0; nj2 < 2; nj2++) {
                int nrow = warp * 32 + nj2 * 16 + b_rsel;
                unsigned so = (unsigned)(nrow * 128 + (((c + b_csel) ^ (nrow & 7)) << 4));
                ldm4(bf[nj2][0], bf[nj2][1], bf[nj2][2], bf[nj2][3], bb + so);
            }
            #pragma unroll
            for (int mi = 0; mi < 2; mi++)
                #pragma unroll
                for (int nj = 0; nj < 4; nj++) {
                    const unsigned* b = bf[nj >> 1];
                    unsigned b0 = (nj & 1) ? b[2] : b[0];
                    unsigned b1 = (nj & 1) ? b[3] : b[1];
                    mma_f16(acc[mi][nj], af[mi][0], af[mi][1], af[mi][2], af[mi][3], b0, b1);
                }
        }
    }

    // stage tile (bias added) to cbuf
    const int colw = warp * 32 + (lane & 3) * 2;
    #pragma unroll
    for (int mi = 0; mi < 2; mi++) {
        int r = mi * 16 + (lane >> 2);
        #pragma unroll
        for (int nj = 0; nj < 4; nj++) {
            int col = colw + nj * 8;
            float b0v = bias[col], b1v = bias[col + 1];
            cbuf[r * ALN_CSTR + col]           = acc[mi][nj][0] + b0v;
            cbuf[r * ALN_CSTR + col + 1]       = acc[mi][nj][1] + b1v;
            cbuf[(r + 8) * ALN_CSTR + col]     = acc[mi][nj][2] + b0v;
            cbuf[(r + 8) * ALN_CSTR + col + 1] = acc[mi][nj][3] + b1v;
        }
    }
    __syncthreads();

    // LayerNorm(resid + tile): warp handles rows warp*4 .. warp*4+3
    #pragma unroll
    for (int rr = 0; rr < 4; rr++) {
        const int r = warp * 4 + rr;
        const size_t grow = (size_t)(row0 + r);
        float v[8];
        float s = 0.f;
        #pragma unroll
        for (int j = 0; j < 8; j++) {
            int c = lane + 32 * j;
            v[j] = cbuf[r * ALN_CSTR + c] + resid[grow * CCH + c];
            s += v[j];
        }
        #pragma unroll
        for (int o = 16; o > 0; o >>= 1) s += __shfl_xor_sync(0xffffffffu, s, o);
        const float mean = s * (1.f / CCH);
        float s2 = 0.f;
        #pragma unroll
        for (int j = 0; j < 8; j++) { float d = v[j] - mean; s2 += d * d; }
        #pragma unroll
        for (int o = 16; o > 0; o >>= 1) s2 += __shfl_xor_sync(0xffffffffu, s2, o);
        const float inv = rsqrtf(s2 * (1.f / CCH) + LN_EPS);
        #pragma unroll
        for (int j = 0; j < 8; j++) {
            int c = lane + 32 * j;
            float y = (v[j] - mean) * inv * g[c] + be[c];
            xout[grow * CCH + c] = y;
            if (WRITE_HALF) x1out[grow * CCH + c] = __float2half_rn(y);
        }
    }
}

// ---------------------------------------------------------------------------
// merged prep: act conversion + border zero + weight transposes, one launch.
// ---------------------------------------------------------------------------
__global__ void prep_kernel(const float* __restrict__ src, const float* __restrict__ pos,
                            __half* __restrict__ q1, __half* __restrict__ s1,
                            __half* __restrict__ valp,
                            const float* __restrict__ w_off, const float* __restrict__ w_attn,
                            const float* __restrict__ w_val, const float* __restrict__ w_out,
                            const float* __restrict__ w1,    const float* __restrict__ w2,
                            __half* __restrict__ d_off, __half* __restrict__ d_attn,
                            __half* __restrict__ d_val, __half* __restrict__ d_out,
                            __half* __restrict__ d_w1,  __half* __restrict__ d_w2) {
    __shared__ float tile[32][33];
    const int bid = blockIdx.x;
    const int tid = threadIdx.x;

    if (bid < 10880) {
        int i = bid * 256 + tid;
        float2 s = ((const float2*)src)[i];
        float2 p = ((const float2*)pos)[i];
        ((__half2*)s1)[i] = __floats2half2_rn(s.x, s.y);
        ((__half2*)q1)[i] = __floats2half2_rn(s.x + p.x, s.y + p.y);
    } else if (bid < 14112) {
        const int gid = (bid - 10880) * 8 + (tid >> 5);
        const int lane = tid & 31;
        int cell = gid % PBATCH;
        int W4, loc;
        if (cell < PB1)      { loc = cell;       W4 = 68; }
        else if (cell < PB2) { loc = cell - PB1; W4 = 36; }
        else if (cell < PB3) { loc = cell - PB2; W4 = 20; }
        else                 { loc = cell - PB3; W4 = 12; }
        const int y = loc / W4, x = loc - y * W4;
        if ((y < 2) | (y >= W4 - 2) | (x < 2) | (x >= W4 - 2)) {
            uint4* p = (uint4*)(valp + (size_t)gid * CCH);
            p[lane] = make_uint4(0u, 0u, 0u, 0u);
        }
    } else {
        int id = bid - 14112;
        const float* W; __half* Bt; int K, N, nx, local;
        if      (id < 64)  { W = w_off;  Bt = d_off;  K = CCH; N = CCH; nx = 8;  local = id; }
        else if (id < 96)  { W = w_attn; Bt = d_attn; K = CCH; N = 128; nx = 4;  local = id - 64; }
        else if (id < 160) { W = w_val;  Bt = d_val;  K = CCH; N = CCH; nx = 8;  local = id - 96; }
        else if (id < 224) { W = w_out;  Bt = d_out;  K = CCH; N = CCH; nx = 8;  local = id - 160; }
        else if (id < 480) { W = w1;     Bt = d_w1;   K = CCH; N = DFF; nx = 32; local = id - 224; }
        else               { W = w2;     Bt = d_w2;   K = DFF; N = CCH; nx = 8;  local = id - 480; }
        const int n0 = (local % nx) * 32, k0 = (local / nx) * 32;
        const int tx = tid & 31, ty = tid >> 5;
        #pragma unroll
        for (int i = 0; i < 4; i++) {
            int k = ty + i * 8;
            tile[k][tx] = W[(size_t)(k0 + k) * N + n0 + tx];
        }
        __syncthreads();
        #pragma unroll
        for (int i = 0; i < 4; i++) {
            int n = ty + i * 8;
            Bt[(size_t)(n0 + n) * K + k0 + tx] = __float2half_rn(tile[tx][n]);
        }
    }
}

// ---------------------------------------------------------------------------
// MSDA: half2 channels, one warp serves two heads.
// ---------------------------------------------------------------------------
__global__ void msda_kernel(const __half* __restrict__ valp,
                            const float* __restrict__ off,
                            const float* __restrict__ logits,
                            const float* __restrict__ refp,
                            __half* __restrict__ out1) {
    const int warp = threadIdx.x >> 5;
    const int lane = threadIdx.x & 31;
    const int hp = warp & 3;
    const int t  = blockIdx.x * 2 + (warp >> 2);
    const int b  = t / LEN;
    const int p  = lane & 15;
    const int h  = hp * 2 + (lane >> 4);
    const int hsel = lane & 16;

    const float* lg = logits + (size_t)t * 128 + h * 16;
    float l0 = lg[p];
    float mx = l0;
    #pragma unroll
    for (int o = 1; o < 16; o <<= 1) mx = fmaxf(mx, __shfl_xor_sync(0xffffffffu, mx, o));
    float e = __expf(l0 - mx);
    float s = e;
    #pragma unroll
    for (int o = 1; o < 16; o <<= 1) s += __shfl_xor_sync(0xffffffffu, s, o);
    const float wgt = e / s;

    const int l  = p >> 2;
    const int Wl = 64 >> l;
    const int W4 = Wl + 4;
    const int base = (l == 0) ? PB0 : (l == 1) ? PB1 : (l == 2) ? PB2 : PB3;
    const float2* off2 = (const float2*)(off + (size_t)t * CCH + h * (NL * NP * 2));
    const float2* ref2 = (const float2*)(refp + (size_t)t * (NL * 2));
    float2 o2 = off2[p];
    float2 r2 = ref2[l];
    const float fW = (float)Wl;
    const float px = fmaf(r2.x, fW, o2.x - 0.5f);
    const float py = fmaf(r2.y, fW, o2.y - 0.5f);
    const float fx = floorf(px), fy = floorf(py);
    const int x0 = (int)fx, y0 = (int)fy;
    const float wx1 = px - fx, wy1 = py - fy;
    const float wx0 = 1.f - wx1, wy0 = 1.f - wy1;
    const int x0c = min(max(x0, -2), Wl);
    const int y0c = min(max(y0, -2), Wl);
    const int rcell = base + (y0c + 2) * W4 + (x0c + 2);
    const float w00 = wgt * wx0 * wy0;
    const float w10 = wgt * wx1 * wy0;
    const float w01 = wgt * wx0 * wy1;
    const float w11 = wgt * wx1 * wy1;

    const __half* vbase = valp + ((size_t)b * PBATCH) * CCH + h * DH + p * 2;
    float accx = 0.f, accy = 0.f;

    #pragma unroll
    for (int q = 0; q < 16; q++) {
        const int W4q = (64 >> (q >> 2)) + 4;
        const int src = q | hsel;
        const int rc  = __shfl_sync(0xffffffffu, rcell, src);
        const float a00 = __shfl_sync(0xffffffffu, w00, src);
        const float a10 = __shfl_sync(0xffffffffu, w10, src);
        const float a01 = __shfl_sync(0xffffffffu, w01, src);
        const float a11 = __shfl_sync(0xffffffffu, w11, src);
        const __half* qp = vbase + (size_t)rc * CCH;
        float2 v00 = __half22float2(*(const __half2*)(qp));
        float2 v10 = __half22float2(*(const __half2*)(qp + CCH));
        float2 v01 = __half22float2(*(const __half2*)(qp + (size_t)W4q * CCH));
        float2 v11 = __half22float2(*(const __half2*)(qp + (size_t)(W4q + 1) * CCH));
        accx = fmaf(a00, v00.x, accx); accy = fmaf(a00, v00.y, accy);
        accx = fmaf(a10, v10.x, accx); accy = fmaf(a10, v10.y, accy);
        accx = fmaf(a01, v01.x, accx); accy = fmaf(a01, v01.y, accy);
        accx = fmaf(a11, v11.x, accx); accy = fmaf(a11, v11.y, accy);
    }
    *(__half2*)(out1 + (size_t)t * CCH + h * DH + p * 2) = __floats2half2_rn(accx, accy);
}

// ---------------------------------------------------------------------------
// launch
// ---------------------------------------------------------------------------
extern "C" void kernel_launch(void* const* d_in, const int* in_sizes, int n_in,
                              void* d_out, int out_size) {
    const float* src   = (const float*)d_in[0];
    const float* pos   = (const float*)d_in[1];
    const float* refp  = (const float*)d_in[2];
    const float* w_off  = (const float*)d_in[6];
    const float* b_off  = (const float*)d_in[7];
    const float* w_attn = (const float*)d_in[8];
    const float* b_attn = (const float*)d_in[9];
    const float* w_val  = (const float*)d_in[10];
    const float* b_val  = (const float*)d_in[11];
    const float* w_out  = (const float*)d_in[12];
    const float* b_out  = (const float*)d_in[13];
    const float* g1     = (const float*)d_in[14];
    const float* be1    = (const float*)d_in[15];
    const float* w1     = (const float*)d_in[16];
    const float* b1     = (const float*)d_in[17];
    const float* w2     = (const float*)d_in[18];
    const float* b2     = (const float*)d_in[19];
    const float* g2     = (const float*)d_in[20];
    const float* be2    = (const float*)d_in[21];
    float* out = (float*)d_out;

    __half *p_q1, *p_src1, *p_msda1, *p_x1, *p_h1, *p_valp;
    __half *p_woffh, *p_wattnh, *p_wvalh, *p_wouth, *p_w1h, *p_w2h;
    float *p_off, *p_aw, *p_x;
    cudaGetSymbolAddress((void**)&p_q1,    g_q1);
    cudaGetSymbolAddress((void**)&p_src1,  g_src1);
    cudaGetSymbolAddress((void**)&p_msda1, g_msda1);
    cudaGetSymbolAddress((void**)&p_x1,    g_x1);
    cudaGetSymbolAddress((void**)&p_h1,    g_h1);
    cudaGetSymbolAddress((void**)&p_valp,  g_valp);
    cudaGetSymbolAddress((void**)&p_woffh, g_woffh);
    cudaGetSymbolAddress((void**)&p_wattnh,g_wattnh);
    cudaGetSymbolAddress((void**)&p_wvalh, g_wvalh);
    cudaGetSymbolAddress((void**)&p_wouth, g_wouth);
    cudaGetSymbolAddress((void**)&p_w1h,   g_w1h);
    cudaGetSymbolAddress((void**)&p_w2h,   g_w2h);
    cudaGetSymbolAddress((void**)&p_off,   g_off);
    cudaGetSymbolAddress((void**)&p_aw,    g_aw);
    cudaGetSymbolAddress((void**)&p_x,     g_x);

    const int M = NTOK;  // 21760 = 340 * 64 = 680 * 32
    const dim3 blk(256);

    const int SM4 = NST * STAGE_SZ;  // 98304
    cudaFuncSetAttribute(proj_gemm,    cudaFuncAttributeMaxDynamicSharedMemorySize, SM4);
    cudaFuncSetAttribute(mma_gemm<1>,  cudaFuncAttributeMaxDynamicSharedMemorySize, SM4);
    cudaFuncSetAttribute(gemm_ln<1>,   cudaFuncAttributeMaxDynamicSharedMemorySize, ALN_SMEM);
    cudaFuncSetAttribute(gemm_ln<0>,   cudaFuncAttributeMaxDynamicSharedMemorySize, ALN_SMEM);

    // merged prep: act conversion + border zero + weight transposes
    prep_kernel<<<14848, blk>>>(src, pos, p_q1, p_src1, p_valp,
                                w_off, w_attn, w_val, w_out, w1, w2,
                                p_woffh, p_wattnh, p_wvalh, p_wouth, p_w1h, p_w2h);

    // fused projections: off / logits / value(padded fp16)
    proj_gemm<<<dim3(5, M / 64), blk, SM4>>>(p_q1, p_src1, p_woffh, p_wattnh, p_wvalh,
                                             b_off, b_attn, b_val, p_off, p_aw, p_valp);
    // MSDA gather (softmax fused, half2 channels, 2 heads per warp)
    msda_kernel<<<NTOK / 2, blk>>>(p_valp, p_off, p_aw, refp, p_msda1);
    // attn_out GEMM + residual(src) + LN1 -> x fp32, x1 fp16
    gemm_ln<1><<<M / 32, blk, ALN_SMEM>>>(p_msda1, p_wouth, b_out, src, g1, be1,
                                          p_x, p_x1, CCH);
    // h = relu(x @ w1 + b1) -> fp16
    mma_gemm<1><<<dim3(8, M / 64), blk, SM4>>>(p_x1, p_w1h, b1, nullptr, p_h1, DFF, CCH);
    // ffn2 GEMM + residual(x) + LN2 -> final output
    gemm_ln<0><<<M / 32, blk, ALN_SMEM>>>(p_h1, p_w2h, b2, p_x, g2, be2,
                                          out, nullptr, DFF);
}

// round 15
// speedup vs baseline: 1.0384x; 1.0384x over previous
#include <cuda_runtime.h>
#include <cuda_fp16.h>
#include <math.h>

// Problem constants
#define NB   4
#define LEN  5440
#define NTOK (NB * LEN)          // 21760
#define CCH  256
#define NH   8
#define DH   32
#define NL   4
#define NP   4
#define DFF  1024
#define LN_EPS 1e-5f

// Padded value layout: per level pad 2 on all sides, fp16.
#define PBATCH 6464
#define PB0 0
#define PB1 4624
#define PB2 5920
#define PB3 6320

// ---------------------------------------------------------------------------
// Scratch
// ---------------------------------------------------------------------------
__device__ __half g_q1   [NTOK * CCH];
__device__ __half g_src1 [NTOK * CCH];
__device__ __half g_msda1[NTOK * CCH];
__device__ __half g_x1   [NTOK * CCH];
__device__ __half g_h1   [NTOK * DFF];
__device__ __half g_valp [NB * PBATCH * CCH];

__device__ float g_off [NTOK * CCH];
__device__ float g_aw  [NTOK * 128];
__device__ float g_x   [NTOK * CCH];
__device__ float g_ffn [NTOK * CCH];

__device__ __half g_woffh [CCH * CCH];
__device__ __half g_wattnh[128 * CCH];
__device__ __half g_wvalh [CCH * CCH];
__device__ __half g_wouth [CCH * CCH];
__device__ __half g_w1h   [DFF * CCH];
__device__ __half g_w2h   [CCH * DFF];

// ---------------------------------------------------------------------------
// helpers
// ---------------------------------------------------------------------------
__device__ __forceinline__ unsigned smem_u32(const void* p) {
    unsigned a;
    asm("{ .reg .u64 t; cvta.to.shared.u64 t, %1; cvt.u32.u64 %0, t; }" : "=r"(a) : "l"(p));
    return a;
}

__device__ __forceinline__ void cp_async16(unsigned dst, const void* src) {
    asm volatile("cp.async.cg.shared.global [%0], [%1], 16;\n" :: "r"(dst), "l"(src));
}
__device__ __forceinline__ void cp_commit() {
    asm volatile("cp.async.commit_group;\n" ::: "memory");
}
template<int N>
__device__ __forceinline__ void cp_wait() {
    asm volatile("cp.async.wait_group %0;\n" :: "n"(N) : "memory");
}

__device__ __forceinline__ void ldm4(unsigned& r0, unsigned& r1, unsigned& r2, unsigned& r3,
                                     unsigned a) {
    asm volatile("ldmatrix.sync.aligned.m8n8.x4.shared.b16 {%0,%1,%2,%3}, [%4];"
                 : "=r"(r0), "=r"(r1), "=r"(r2), "=r"(r3) : "r"(a));
}

__device__ __forceinline__ void mma_f16(float c[4],
                                        unsigned a0, unsigned a1, unsigned a2, unsigned a3,
                                        unsigned b0, unsigned b1) {
    asm volatile(
        "mma.sync.aligned.m16n8k16.row.col.f32.f16.f16.f32 "
        "{%0,%1,%2,%3},{%4,%5,%6,%7},{%8,%9},{%0,%1,%2,%3};"
        : "+f"(c[0]), "+f"(c[1]), "+f"(c[2]), "+f"(c[3])
        : "r"(a0), "r"(a1), "r"(a2), "r"(a3), "r"(b0), "r"(b1));
}

// token -> padded value row base (channel 0)
__device__ __forceinline__ __half* valp_row(__half* Vp, int t) {
    int b = t / LEN;
    int pos = t - b * LEN;
    int base, W4, ys, m, loc;
    if (pos < 4096)      { loc = pos;        base = PB0; W4 = 68; ys = 6; m = 63; }
    else if (pos < 5120) { loc = pos - 4096; base = PB1; W4 = 36; ys = 5; m = 31; }
    else if (pos < 5376) { loc = pos - 5120; base = PB2; W4 = 20; ys = 4; m = 15; }
    else                 { loc = pos - 5376; base = PB3; W4 = 12; ys = 3; m = 7; }
    int y = loc >> ys, x = loc & m;
    return Vp + ((size_t)b * PBATCH + base + (y + 2) * W4 + (x + 2)) * CCH;
}

// ===========================================================================
// GEMM variant A (BM=64, BN=128, warp 32x32, NST=4) — used for ffn2.
// ===========================================================================
#define NST 4
#define GBM 64
#define A_BYTES (GBM * 128)
#define STAGE_SZ ((GBM + 128) * 128)   // 24576

__device__ __forceinline__ void gemm_load_stage(unsigned sb, int stage,
                                                const __half* A, const __half* B,
                                                int K, int kt, int tid) {
    const unsigned abase = sb + stage * STAGE_SZ;
    const unsigned bbase = abase + A_BYTES;
    const __half* ag = A + kt * 64;
    const __half* bg = B + kt * 64;
    #pragma unroll
    for (int i = 0; i < 2; i++) {
        int id = tid + i * 256;
        int r = id >> 3, c = id & 7;
        unsigned off = (unsigned)(r * 128 + ((c ^ (r & 7)) << 4));
        cp_async16(abase + off, ag + (size_t)r * K + c * 8);
    }
    #pragma unroll
    for (int i = 0; i < 4; i++) {
        int id = tid + i * 256;
        int r = id >> 3, c = id & 7;
        unsigned off = (unsigned)(r * 128 + ((c ^ (r & 7)) << 4));
        cp_async16(bbase + off, bg + (size_t)r * K + c * 8);
    }
    cp_commit();
}

__global__ __launch_bounds__(256, 2)
void mma_gemm64(const __half* __restrict__ A, const __half* __restrict__ Bt,
                const float* __restrict__ bias, float* __restrict__ Cf,
                int N, int K) {
    extern __shared__ __align__(1024) char smem[];
    const unsigned sb = smem_u32(smem);
    const int tid = threadIdx.x;
    const int warp = tid >> 5, lane = tid & 31;
    const int wm = warp & 1, wn = warp >> 1;
    const int bx = blockIdx.x, by = blockIdx.y;
    const __half* Ab = A + (size_t)by * GBM * K;
    const __half* Bb = Bt + (size_t)bx * 128 * (size_t)K;
    const float* biasb = bias + bx * 128;
    float* Cb = Cf + bx * 128;
    const int KT = K >> 6;

    float acc[2][4][4];
    #pragma unroll
    for (int i = 0; i < 2; i++)
        #pragma unroll
        for (int j = 0; j < 4; j++)
            #pragma unroll
            for (int r = 0; r < 4; r++) acc[i][j][r] = 0.f;

    #pragma unroll
    for (int s = 0; s < NST - 1; s++) {
        if (s < KT) gemm_load_stage(sb, s, Ab, Bb, K, s, tid);
        else        cp_commit();
    }

    const int a_row  = (lane & 15);
    const int a_csel = (lane >> 4);
    const int b_rsel = ((lane >> 4) << 3) + (lane & 7);
    const int b_csel = ((lane >> 3) & 1);

    for (int kt = 0; kt < KT; kt++) {
        const int stage = kt % NST;
        cp_wait<NST - 2>();
        __syncthreads();
        if (kt + NST - 1 < KT)
            gemm_load_stage(sb, (kt + NST - 1) % NST, Ab, Bb, K, kt + NST - 1, tid);
        else
            cp_commit();

        const unsigned ab = sb + stage * STAGE_SZ;
        const unsigned bb = ab + A_BYTES;

        #pragma unroll
        for (int kk = 0; kk < 4; kk++) {
            const int c = kk * 2;
            unsigned af[2][4], bf[2][4];
            #pragma unroll
            for (int mi = 0; mi < 2; mi++) {
                int row = wm * 32 + mi * 16 + a_row;
                unsigned so = (unsigned)(row * 128 + (((c + a_csel) ^ (row & 7)) << 4));
                ldm4(af[mi][0], af[mi][1], af[mi][2], af[mi][3], ab + so);
            }
            #pragma unroll
            for (int nj2 = 0; nj2 < 2; nj2++) {
                int nrow = wn * 32 + nj2 * 16 + b_rsel;
                unsigned so = (unsigned)(nrow * 128 + (((c + b_csel) ^ (nrow & 7)) << 4));
                ldm4(bf[nj2][0], bf[nj2][1], bf[nj2][2], bf[nj2][3], bb + so);
            }
            #pragma unroll
            for (int mi = 0; mi < 2; mi++)
                #pragma unroll
                for (int nj = 0; nj < 4; nj++) {
                    const unsigned* b = bf[nj >> 1];
                    unsigned b0 = (nj & 1) ? b[2] : b[0];
                    unsigned b1 = (nj & 1) ? b[3] : b[1];
                    mma_f16(acc[mi][nj], af[mi][0], af[mi][1], af[mi][2], af[mi][3], b0, b1);
                }
        }
    }

    const int col0 = wn * 32 + (lane & 3) * 2;
    #pragma unroll
    for (int mi = 0; mi < 2; mi++) {
        int row = by * GBM + wm * 32 + mi * 16 + (lane >> 2);
        #pragma unroll
        for (int nj = 0; nj < 4; nj++) {
            int col = col0 + nj * 8;
            float b0v = biasb[col], b1v = biasb[col + 1];
            *(float2*)(Cb + (size_t)row * N + col) =
                make_float2(acc[mi][nj][0] + b0v, acc[mi][nj][1] + b1v);
            *(float2*)(Cb + (size_t)(row + 8) * N + col) =
                make_float2(acc[mi][nj][2] + b0v, acc[mi][nj][3] + b1v);
        }
    }
}

// ===========================================================================
// GEMM variant B (BM=128, BN=128, 8 warps 4m x 2n, warp 32x64, NST=3)
// — used for proj and ffn1. OUT_MODE 0: fp32; 1: relu+fp16; 2: padded value.
// ===========================================================================
#define NST1 3
#define STAGE1 (256 * 128)   // 32768 (A 128 rows + B 128 rows)

__device__ __forceinline__ void load_stage128(unsigned sb, int stage,
                                              const __half* A, const __half* B,
                                              int K, int kt, int tid) {
    const unsigned abase = sb + stage * STAGE1;
    const unsigned bbase = abase + 128 * 128;
    const __half* ag = A + kt * 64;
    const __half* bg = B + kt * 64;
    #pragma unroll
    for (int i = 0; i < 4; i++) {
        int id = tid + i * 256;
        int r = id >> 3, c = id & 7;
        unsigned off = (unsigned)(r * 128 + ((c ^ (r & 7)) << 4));
        cp_async16(abase + off, ag + (size_t)r * K + c * 8);
    }
    #pragma unroll
    for (int i = 0; i < 4; i++) {
        int id = tid + i * 256;
        int r = id >> 3, c = id & 7;
        unsigned off = (unsigned)(r * 128 + ((c ^ (r & 7)) << 4));
        cp_async16(bbase + off, bg + (size_t)r * K + c * 8);
    }
    cp_commit();
}

template<int OUT_MODE>
__device__ __forceinline__ void gemm_body128(const __half* A, const __half* B,
                                             const float* bias, float* Cf, __half* C2,
                                             int N, int K, int row_base, int col_base,
                                             char* smem) {
    const unsigned sb = smem_u32(smem);
    const int tid = threadIdx.x;
    const int warp = tid >> 5, lane = tid & 31;
    const int wm = warp >> 1, wn = warp & 1;   // 4m x 2n
    const int KT = K >> 6;

    float acc[2][8][4];
    #pragma unroll
    for (int i = 0; i < 2; i++)
        #pragma unroll
        for (int j = 0; j < 8; j++)
            #pragma unroll
            for (int r = 0; r < 4; r++) acc[i][j][r] = 0.f;

    #pragma unroll
    for (int s = 0; s < NST1 - 1; s++) {
        if (s < KT) load_stage128(sb, s, A, B, K, s, tid);
        else        cp_commit();
    }

    const int a_row  = (lane & 15);
    const int a_csel = (lane >> 4);
    const int b_rsel = ((lane >> 4) << 3) + (lane & 7);
    const int b_csel = ((lane >> 3) & 1);

    for (int kt = 0; kt < KT; kt++) {
        const int stage = kt % NST1;
        cp_wait<NST1 - 2>();
        __syncthreads();
        if (kt + NST1 - 1 < KT)
            load_stage128(sb, (kt + NST1 - 1) % NST1, A, B, K, kt + NST1 - 1, tid);
        else
            cp_commit();

        const unsigned ab = sb + stage * STAGE1;
        const unsigned bb = ab + 128 * 128;

        #pragma unroll
        for (int kk = 0; kk < 4; kk++) {
            const int c = kk * 2;
            unsigned af[2][4], bf[4][4];
            #pragma unroll
            for (int mi = 0; mi < 2; mi++) {
                int row = wm * 32 + mi * 16 + a_row;
                unsigned so = (unsigned)(row * 128 + (((c + a_csel) ^ (row & 7)) << 4));
                ldm4(af[mi][0], af[mi][1], af[mi][2], af[mi][3], ab + so);
            }
            #pragma unroll
            for (int nj2 = 0; nj2 < 4; nj2++) {
                int nrow = wn * 64 + nj2 * 16 + b_rsel;
                unsigned so = (unsigned)(nrow * 128 + (((c + b_csel) ^ (nrow & 7)) << 4));
                ldm4(bf[nj2][0], bf[nj2][1], bf[nj2][2], bf[nj2][3], bb + so);
            }
            #pragma unroll
            for (int mi = 0; mi < 2; mi++)
                #pragma unroll
                for (int nj = 0; nj < 8; nj++) {
                    const unsigned* b = bf[nj >> 1];
                    unsigned b0 = (nj & 1) ? b[2] : b[0];
                    unsigned b1 = (nj & 1) ? b[3] : b[1];
                    mma_f16(acc[mi][nj], af[mi][0], af[mi][1], af[mi][2], af[mi][3], b0, b1);
                }
        }
    }

    const int col0 = wn * 64 + (lane & 3) * 2;
    #pragma unroll
    for (int mi = 0; mi < 2; mi++) {
        int row = row_base + wm * 32 + mi * 16 + (lane >> 2);
        __half *p0 = nullptr, *p1 = nullptr;
        if (OUT_MODE == 2) {
            p0 = valp_row(C2, row) + col_base;
            p1 = valp_row(C2, row + 8) + col_base;
        }
        #pragma unroll
        for (int nj = 0; nj < 8; nj++) {
            int col = col0 + nj * 8;
            float b0v = bias[col], b1v = bias[col + 1];
            float v00 = acc[mi][nj][0] + b0v, v01 = acc[mi][nj][1] + b1v;
            float v10 = acc[mi][nj][2] + b0v, v11 = acc[mi][nj][3] + b1v;
            if (OUT_MODE == 0) {
                *(float2*)(Cf + (size_t)row * N + col)       = make_float2(v00, v01);
                *(float2*)(Cf + (size_t)(row + 8) * N + col) = make_float2(v10, v11);
            } else if (OUT_MODE == 1) {
                v00 = fmaxf(v00, 0.f); v01 = fmaxf(v01, 0.f);
                v10 = fmaxf(v10, 0.f); v11 = fmaxf(v11, 0.f);
                *(__half2*)(C2 + (size_t)row * N + col)       = __floats2half2_rn(v00, v01);
                *(__half2*)(C2 + (size_t)(row + 8) * N + col) = __floats2half2_rn(v10, v11);
            } else {
                *(__half2*)(p0 + col) = __floats2half2_rn(v00, v01);
                *(__half2*)(p1 + col) = __floats2half2_rn(v10, v11);
            }
        }
    }
}

// ffn1 GEMM: BM=128, relu + fp16 out
__global__ __launch_bounds__(256, 2)
void ffn1_gemm(const __half* __restrict__ A, const __half* __restrict__ Bt,
               const float* __restrict__ bias, __half* __restrict__ C2,
               int N, int K) {
    extern __shared__ __align__(1024) char smem[];
    const int bx = blockIdx.x, by = blockIdx.y;
    gemm_body128<1>(A + (size_t)by * 128 * K,
                    Bt + (size_t)bx * 128 * (size_t)K,
                    bias + bx * 128, nullptr, C2 + bx * 128,
                    N, K, by * 128, 0, smem);
}

// fused projection GEMM (BM=128): bx selects {off0, off1, logits, val0, val1}
__global__ __launch_bounds__(256, 2)
void proj_gemm(const __half* __restrict__ q1, const __half* __restrict__ src1,
               const __half* __restrict__ woffh, const __half* __restrict__ wattnh,
               const __half* __restrict__ wvalh,
               const float* __restrict__ b_off, const float* __restrict__ b_attn,
               const float* __restrict__ b_val,
               float* __restrict__ c_off, float* __restrict__ c_aw,
               __half* __restrict__ valp) {
    extern __shared__ __align__(1024) char smem[];
    const int bx = blockIdx.x, by = blockIdx.y;
    const int K = CCH;

    if (bx < 2) {
        gemm_body128<0>(q1 + (size_t)by * 128 * K, woffh + (size_t)bx * 128 * K,
                        b_off + bx * 128, c_off + bx * 128, nullptr,
                        CCH, K, by * 128, 0, smem);
    } else if (bx == 2) {
        gemm_body128<0>(q1 + (size_t)by * 128 * K, wattnh,
                        b_attn, c_aw, nullptr,
                        128, K, by * 128, 0, smem);
    } else {
        int s = bx - 3;
        gemm_body128<2>(src1 + (size_t)by * 128 * K, wvalh + (size_t)s * 128 * K,
                        b_val + s * 128, nullptr, valp,
                        CCH, K, by * 128, s * 128, smem);
    }
}

// ---------------------------------------------------------------------------
// Fused attn GEMM(BM=32, BN=256) + residual + LN1 (round-13, proven).
// ---------------------------------------------------------------------------
#define ALN_STAGE ((32 + 256) * 128)        // 36864
#define ALN_CSTR 264
#define ALN_SMEM (2 * ALN_STAGE + 32 * ALN_CSTR * 4)   // 107520

__global__ __launch_bounds__(256, 2)
void attn_ln_gemm(const __half* __restrict__ A, const __half* __restrict__ Bt,
                  const float* __restrict__ bias, const float* __restrict__ src,
                  const float* __restrict__ g1, const float* __restrict__ be1,
                  float* __restrict__ xout, __half* __restrict__ x1out) {
    extern __shared__ __align__(1024) char smem[];
    const unsigned sb = smem_u32(smem);
    float* cbuf = (float*)(smem + 2 * ALN_STAGE);
    const int tid = threadIdx.x;
    const int warp = tid >> 5, lane = tid & 31;
    const int row0 = blockIdx.x * 32;
    const int K = CCH;
    const int KT = 4;

    float acc[2][4][4];
    #pragma unroll
    for (int i = 0; i < 2; i++)
        #pragma unroll
        for (int j = 0; j < 4; j++)
            #pragma unroll
            for (int r = 0; r < 4; r++) acc[i][j][r] = 0.f;

    {
        const unsigned abase = sb;
        const unsigned bbase = sb + 32 * 128;
        const __half* ag = A + (size_t)row0 * K;
        {
            int r = tid >> 3, c = tid & 7;
            unsigned off = (unsigned)(r * 128 + ((c ^ (r & 7)) << 4));
            cp_async16(abase + off, ag + (size_t)r * K + c * 8);
        }
        #pragma unroll
        for (int i = 0; i < 8; i++) {
            int id = tid + i * 256;
            int r = id >> 3, c = id & 7;
            unsigned off = (unsigned)(r * 128 + ((c ^ (r & 7)) << 4));
            cp_async16(bbase + off, Bt + (size_t)r * K + c * 8);
        }
        cp_commit();
    }

    const int a_row  = (lane & 15);
    const int a_csel = (lane >> 4);
    const int b_rsel = ((lane >> 4) << 3) + (lane & 7);
    const int b_csel = ((lane >> 3) & 1);

    for (int kt = 0; kt < KT; kt++) {
        const int stage = kt & 1;
        cp_wait<0>();
        __syncthreads();
        if (kt + 1 < KT) {
            const unsigned abase = sb + (stage ^ 1) * ALN_STAGE;
            const unsigned bbase = abase + 32 * 128;
            const __half* ag = A + (size_t)row0 * K + (kt + 1) * 64;
            const __half* bg = Bt + (kt + 1) * 64;
            {
                int r = tid >> 3, c = tid & 7;
                unsigned off = (unsigned)(r * 128 + ((c ^ (r & 7)) << 4));
                cp_async16(abase + off, ag + (size_t)r * K + c * 8);
            }
            #pragma unroll
            for (int i = 0; i < 8; i++) {
                int id = tid + i * 256;
                int r = id >> 3, c = id & 7;
                unsigned off = (unsigned)(r * 128 + ((c ^ (r & 7)) << 4));
                cp_async16(bbase + off, bg + (size_t)r * K + c * 8);
            }
            cp_commit();
        }

        const unsigned ab = sb + stage * ALN_STAGE;
        const unsigned bb = ab + 32 * 128;

        #pragma unroll
        for (int kk = 0; kk < 4; kk++) {
            const int c = kk * 2;
            unsigned af[2][4], bf[2][4];
            #pragma unroll
            for (int mi = 0; mi < 2; mi++) {
                int row = mi * 16 + a_row;
                unsigned so = (unsigned)(row * 128 + (((c + a_csel) ^ (row & 7)) << 4));
                ldm4(af[mi][0], af[mi][1], af[mi][2], af[mi][3], ab + so);
            }
            #pragma unroll
            for (int nj2 = 0; nj2 < 2; nj2++) {
                int nrow = warp * 32 + nj2 * 16 + b_rsel;
                unsigned so = (unsigned)(nrow * 128 + (((c + b_csel) ^ (nrow & 7)) << 4));
                ldm4(bf[nj2][0], bf[nj2][1], bf[nj2][2], bf[nj2][3], bb + so);
            }
            #pragma unroll
            for (int mi = 0; mi < 2; mi++)
                #pragma unroll
                for (int nj = 0; nj < 4; nj++) {
                    const unsigned* b = bf[nj >> 1];
                    unsigned b0 = (nj & 1) ? b[2] : b[0];
                    unsigned b1 = (nj & 1) ? b[3] : b[1];
                    mma_f16(acc[mi][nj], af[mi][0], af[mi][1], af[mi][2], af[mi][3], b0, b1);
                }
        }
    }

    const int colw = warp * 32 + (lane & 3) * 2;
    #pragma unroll
    for (int mi = 0; mi < 2; mi++) {
        int r = mi * 16 + (lane >> 2);
        #pragma unroll
        for (int nj = 0; nj < 4; nj++) {
            int col = colw + nj * 8;
            float b0v = bias[col], b1v = bias[col + 1];
            cbuf[r * ALN_CSTR + col]           = acc[mi][nj][0] + b0v;
            cbuf[r * ALN_CSTR + col + 1]       = acc[mi][nj][1] + b1v;
            cbuf[(r + 8) * ALN_CSTR + col]     = acc[mi][nj][2] + b0v;
            cbuf[(r + 8) * ALN_CSTR + col + 1] = acc[mi][nj][3] + b1v;
        }
    }
    __syncthreads();

    #pragma unroll
    for (int rr = 0; rr < 4; rr++) {
        const int r = warp * 4 + rr;
        const size_t grow = (size_t)(row0 + r);
        float v[8];
        float s = 0.f;
        #pragma unroll
        for (int j = 0; j < 8; j++) {
            int c = lane + 32 * j;
            v[j] = cbuf[r * ALN_CSTR + c] + src[grow * CCH + c];
            s += v[j];
        }
        #pragma unroll
        for (int o = 16; o > 0; o >>= 1) s += __shfl_xor_sync(0xffffffffu, s, o);
        const float mean = s * (1.f / CCH);
        float s2 = 0.f;
        #pragma unroll
        for (int j = 0; j < 8; j++) { float d = v[j] - mean; s2 += d * d; }
        #pragma unroll
        for (int o = 16; o > 0; o >>= 1) s2 += __shfl_xor_sync(0xffffffffu, s2, o);
        const float inv = rsqrtf(s2 * (1.f / CCH) + LN_EPS);
        #pragma unroll
        for (int j = 0; j < 8; j++) {
            int c = lane + 32 * j;
            float y = (v[j] - mean) * inv * g1[c] + be1[c];
            xout[grow * CCH + c]  = y;
            x1out[grow * CCH + c] = __float2half_rn(y);
        }
    }
}

// ---------------------------------------------------------------------------
// merged prep: act conversion + border zero + weight transposes, one launch.
// ---------------------------------------------------------------------------
__global__ void prep_kernel(const float* __restrict__ src, const float* __restrict__ pos,
                            __half* __restrict__ q1, __half* __restrict__ s1,
                            __half* __restrict__ valp,
                            const float* __restrict__ w_off, const float* __restrict__ w_attn,
                            const float* __restrict__ w_val, const float* __restrict__ w_out,
                            const float* __restrict__ w1,    const float* __restrict__ w2,
                            __half* __restrict__ d_off, __half* __restrict__ d_attn,
                            __half* __restrict__ d_val, __half* __restrict__ d_out,
                            __half* __restrict__ d_w1,  __half* __restrict__ d_w2) {
    __shared__ float tile[32][33];
    const int bid = blockIdx.x;
    const int tid = threadIdx.x;

    if (bid < 10880) {
        int i = bid * 256 + tid;
        float2 s = ((const float2*)src)[i];
        float2 p = ((const float2*)pos)[i];
        ((__half2*)s1)[i] = __floats2half2_rn(s.x, s.y);
        ((__half2*)q1)[i] = __floats2half2_rn(s.x + p.x, s.y + p.y);
    } else if (bid < 14112) {
        const int gid = (bid - 10880) * 8 + (tid >> 5);
        const int lane = tid & 31;
        int cell = gid % PBATCH;
        int W4, loc;
        if (cell < PB1)      { loc = cell;       W4 = 68; }
        else if (cell < PB2) { loc = cell - PB1; W4 = 36; }
        else if (cell < PB3) { loc = cell - PB2; W4 = 20; }
        else                 { loc = cell - PB3; W4 = 12; }
        const int y = loc / W4, x = loc - y * W4;
        if ((y < 2) | (y >= W4 - 2) | (x < 2) | (x >= W4 - 2)) {
            uint4* p = (uint4*)(valp + (size_t)gid * CCH);
            p[lane] = make_uint4(0u, 0u, 0u, 0u);
        }
    } else {
        int id = bid - 14112;
        const float* W; __half* Bt; int K, N, nx, local;
        if      (id < 64)  { W = w_off;  Bt = d_off;  K = CCH; N = CCH; nx = 8;  local = id; }
        else if (id < 96)  { W = w_attn; Bt = d_attn; K = CCH; N = 128; nx = 4;  local = id - 64; }
        else if (id < 160) { W = w_val;  Bt = d_val;  K = CCH; N = CCH; nx = 8;  local = id - 96; }
        else if (id < 224) { W = w_out;  Bt = d_out;  K = CCH; N = CCH; nx = 8;  local = id - 160; }
        else if (id < 480) { W = w1;     Bt = d_w1;   K = CCH; N = DFF; nx = 32; local = id - 224; }
        else               { W = w2;     Bt = d_w2;   K = DFF; N = CCH; nx = 8;  local = id - 480; }
        const int n0 = (local % nx) * 32, k0 = (local / nx) * 32;
        const int tx = tid & 31, ty = tid >> 5;
        #pragma unroll
        for (int i = 0; i < 4; i++) {
            int k = ty + i * 8;
            tile[k][tx] = W[(size_t)(k0 + k) * N + n0 + tx];
        }
        __syncthreads();
        #pragma unroll
        for (int i = 0; i < 4; i++) {
            int n = ty + i * 8;
            Bt[(size_t)(n0 + n) * K + k0 + tx] = __float2half_rn(tile[tx][n]);
        }
    }
}

// ---------------------------------------------------------------------------
// MSDA: half2 channels, one warp serves two heads.
// ---------------------------------------------------------------------------
__global__ void msda_kernel(const __half* __restrict__ valp,
                            const float* __restrict__ off,
                            const float* __restrict__ logits,
                            const float* __restrict__ refp,
                            __half* __restrict__ out1) {
    const int warp = threadIdx.x >> 5;
    const int lane = threadIdx.x & 31;
    const int hp = warp & 3;
    const int t  = blockIdx.x * 2 + (warp >> 2);
    const int b  = t / LEN;
    const int p  = lane & 15;
    const int h  = hp * 2 + (lane >> 4);
    const int hsel = lane & 16;

    const float* lg = logits + (size_t)t * 128 + h * 16;
    float l0 = lg[p];
    float mx = l0;
    #pragma unroll
    for (int o = 1; o < 16; o <<= 1) mx = fmaxf(mx, __shfl_xor_sync(0xffffffffu, mx, o));
    float e = __expf(l0 - mx);
    float s = e;
    #pragma unroll
    for (int o = 1; o < 16; o <<= 1) s += __shfl_xor_sync(0xffffffffu, s, o);
    const float wgt = e / s;

    const int l  = p >> 2;
    const int Wl = 64 >> l;
    const int W4 = Wl + 4;
    const int base = (l == 0) ? PB0 : (l == 1) ? PB1 : (l == 2) ? PB2 : PB3;
    const float2* off2 = (const float2*)(off + (size_t)t * CCH + h * (NL * NP * 2));
    const float2* ref2 = (const float2*)(refp + (size_t)t * (NL * 2));
    float2 o2 = off2[p];
    float2 r2 = ref2[l];
    const float fW = (float)Wl;
    const float px = fmaf(r2.x, fW, o2.x - 0.5f);
    const float py = fmaf(r2.y, fW, o2.y - 0.5f);
    const float fx = floorf(px), fy = floorf(py);
    const int x0 = (int)fx, y0 = (int)fy;
    const float wx1 = px - fx, wy1 = py - fy;
    const float wx0 = 1.f - wx1, wy0 = 1.f - wy1;
    const int x0c = min(max(x0, -2), Wl);
    const int y0c = min(max(y0, -2), Wl);
    const int rcell = base + (y0c + 2) * W4 + (x0c + 2);
    const float w00 = wgt * wx0 * wy0;
    const float w10 = wgt * wx1 * wy0;
    const float w01 = wgt * wx0 * wy1;
    const float w11 = wgt * wx1 * wy1;

    const __half* vbase = valp + ((size_t)b * PBATCH) * CCH + h * DH + p * 2;
    float accx = 0.f, accy = 0.f;

    #pragma unroll
    for (int q = 0; q < 16; q++) {
        const int W4q = (64 >> (q >> 2)) + 4;
        const int src = q | hsel;
        const int rc  = __shfl_sync(0xffffffffu, rcell, src);
        const float a00 = __shfl_sync(0xffffffffu, w00, src);
        const float a10 = __shfl_sync(0xffffffffu, w10, src);
        const float a01 = __shfl_sync(0xffffffffu, w01, src);
        const float a11 = __shfl_sync(0xffffffffu, w11, src);
        const __half* qp = vbase + (size_t)rc * CCH;
        float2 v00 = __half22float2(*(const __half2*)(qp));
        float2 v10 = __half22float2(*(const __half2*)(qp + CCH));
        float2 v01 = __half22float2(*(const __half2*)(qp + (size_t)W4q * CCH));
        float2 v11 = __half22float2(*(const __half2*)(qp + (size_t)(W4q + 1) * CCH));
        accx = fmaf(a00, v00.x, accx); accy = fmaf(a00, v00.y, accy);
        accx = fmaf(a10, v10.x, accx); accy = fmaf(a10, v10.y, accy);
        accx = fmaf(a01, v01.x, accx); accy = fmaf(a01, v01.y, accy);
        accx = fmaf(a11, v11.x, accx); accy = fmaf(a11, v11.y, accy);
    }
    *(__half2*)(out1 + (size_t)t * CCH + h * DH + p * 2) = __floats2half2_rn(accx, accy);
}

// ---------------------------------------------------------------------------
// LayerNorm over C=256 of (a+b): warp per row (final LN2).
// ---------------------------------------------------------------------------
__global__ void ln_kernel(const float* __restrict__ a, const float* __restrict__ b,
                          const float* __restrict__ g, const float* __restrict__ be,
                          float* __restrict__ out, int rows) {
    const int row = blockIdx.x * (blockDim.x >> 5) + (threadIdx.x >> 5);
    const int lane = threadIdx.x & 31;
    if (row >= rows) return;

    const float* pa = a + (size_t)row * CCH;
    const float* pb = b + (size_t)row * CCH;
    float v[8];
    float s = 0.f;
    #pragma unroll
    for (int j = 0; j < 8; j++) {
        int c = lane + 32 * j;
        v[j] = pa[c] + pb[c];
        s += v[j];
    }
    #pragma unroll
    for (int o = 16; o > 0; o >>= 1) s += __shfl_xor_sync(0xffffffffu, s, o);
    const float mean = s * (1.f / CCH);
    float s2 = 0.f;
    #pragma unroll
    for (int j = 0; j < 8; j++) { float d = v[j] - mean; s2 += d * d; }
    #pragma unroll
    for (int o = 16; o > 0; o >>= 1) s2 += __shfl_xor_sync(0xffffffffu, s2, o);
    const float inv = rsqrtf(s2 * (1.f / CCH) + LN_EPS);

    #pragma unroll
    for (int j = 0; j < 8; j++) {
        int c = lane + 32 * j;
        out[(size_t)row * CCH + c] = (v[j] - mean) * inv * g[c] + be[c];
    }
}

// ---------------------------------------------------------------------------
// launch
// ---------------------------------------------------------------------------
extern "C" void kernel_launch(void* const* d_in, const int* in_sizes, int n_in,
                              void* d_out, int out_size) {
    const float* src   = (const float*)d_in[0];
    const float* pos   = (const float*)d_in[1];
    const float* refp  = (const float*)d_in[2];
    const float* w_off  = (const float*)d_in[6];
    const float* b_off  = (const float*)d_in[7];
    const float* w_attn = (const float*)d_in[8];
    const float* b_attn = (const float*)d_in[9];
    const float* w_val  = (const float*)d_in[10];
    const float* b_val  = (const float*)d_in[11];
    const float* w_out  = (const float*)d_in[12];
    const float* b_out  = (const float*)d_in[13];
    const float* g1     = (const float*)d_in[14];
    const float* be1    = (const float*)d_in[15];
    const float* w1     = (const float*)d_in[16];
    const float* b1     = (const float*)d_in[17];
    const float* w2     = (const float*)d_in[18];
    const float* b2     = (const float*)d_in[19];
    const float* g2     = (const float*)d_in[20];
    const float* be2    = (const float*)d_in[21];
    float* out = (float*)d_out;

    __half *p_q1, *p_src1, *p_msda1, *p_x1, *p_h1, *p_valp;
    __half *p_woffh, *p_wattnh, *p_wvalh, *p_wouth, *p_w1h, *p_w2h;
    float *p_off, *p_aw, *p_x, *p_ffn;
    cudaGetSymbolAddress((void**)&p_q1,    g_q1);
    cudaGetSymbolAddress((void**)&p_src1,  g_src1);
    cudaGetSymbolAddress((void**)&p_msda1, g_msda1);
    cudaGetSymbolAddress((void**)&p_x1,    g_x1);
    cudaGetSymbolAddress((void**)&p_h1,    g_h1);
    cudaGetSymbolAddress((void**)&p_valp,  g_valp);
    cudaGetSymbolAddress((void**)&p_woffh, g_woffh);
    cudaGetSymbolAddress((void**)&p_wattnh,g_wattnh);
    cudaGetSymbolAddress((void**)&p_wvalh, g_wvalh);
    cudaGetSymbolAddress((void**)&p_wouth, g_wouth);
    cudaGetSymbolAddress((void**)&p_w1h,   g_w1h);
    cudaGetSymbolAddress((void**)&p_w2h,   g_w2h);
    cudaGetSymbolAddress((void**)&p_off,   g_off);
    cudaGetSymbolAddress((void**)&p_aw,    g_aw);
    cudaGetSymbolAddress((void**)&p_x,     g_x);
    cudaGetSymbolAddress((void**)&p_ffn,   g_ffn);

    const int M = NTOK;  // 21760 = 170 * 128 = 340 * 64 = 680 * 32
    const dim3 blk(256);

    const int SM_A = NST  * STAGE_SZ;   // 98304 (BM=64 path)
    const int SM_B = NST1 * STAGE1;     // 98304 (BM=128 path)
    cudaFuncSetAttribute(proj_gemm,    cudaFuncAttributeMaxDynamicSharedMemorySize, SM_B);
    cudaFuncSetAttribute(ffn1_gemm,    cudaFuncAttributeMaxDynamicSharedMemorySize, SM_B);
    cudaFuncSetAttribute(mma_gemm64,   cudaFuncAttributeMaxDynamicSharedMemorySize, SM_A);
    cudaFuncSetAttribute(attn_ln_gemm, cudaFuncAttributeMaxDynamicSharedMemorySize, ALN_SMEM);

    // merged prep: act conversion + border zero + weight transposes
    prep_kernel<<<14848, blk>>>(src, pos, p_q1, p_src1, p_valp,
                                w_off, w_attn, w_val, w_out, w1, w2,
                                p_woffh, p_wattnh, p_wvalh, p_wouth, p_w1h, p_w2h);

    // fused projections (BM=128): off / logits / value(padded fp16)
    proj_gemm<<<dim3(5, M / 128), blk, SM_B>>>(p_q1, p_src1, p_woffh, p_wattnh, p_wvalh,
                                               b_off, b_attn, b_val, p_off, p_aw, p_valp);
    // MSDA gather (softmax fused, half2 channels, 2 heads per warp)
    msda_kernel<<<NTOK / 2, blk>>>(p_valp, p_off, p_aw, refp, p_msda1);
    // attn_out GEMM + residual(src) + LN1 -> x fp32, x1 fp16
    attn_ln_gemm<<<M / 32, blk, ALN_SMEM>>>(p_msda1, p_wouth, b_out, src, g1, be1, p_x, p_x1);
    // h = relu(x @ w1 + b1) -> fp16 (BM=128)
    ffn1_gemm<<<dim3(8, M / 128), blk, SM_B>>>(p_x1, p_w1h, b1, p_h1, DFF, CCH);
    // ffn = h @ w2 + b2 (BM=64 path, wave-balanced)
    mma_gemm64<<<dim3(2, M / 64), blk, SM_A>>>(p_h1, p_w2h, b2, p_ffn, CCH, DFF);
    // out = LN(x + ffn)
    ln_kernel<<<(NTOK + 7) / 8, blk>>>(p_x, p_ffn, g2, be2, out, NTOK);
}

// round 16
// speedup vs baseline: 1.0511x; 1.0122x over previous
#include <cuda_runtime.h>
#include <cuda_fp16.h>
#include <math.h>

// Problem constants
#define NB   4
#define LEN  5440
#define NTOK (NB * LEN)          // 21760
#define CCH  256
#define NH   8
#define DH   32
#define NL   4
#define NP   4
#define DFF  1024
#define LN_EPS 1e-5f

// Padded value layout: per level pad 2 on all sides, fp16.
#define PBATCH 6464
#define PB0 0
#define PB1 4624
#define PB2 5920
#define PB3 6320

// ---------------------------------------------------------------------------
// Scratch
// ---------------------------------------------------------------------------
__device__ __half g_q1   [NTOK * CCH];
__device__ __half g_src1 [NTOK * CCH];
__device__ __half g_msda1[NTOK * CCH];    // msda out; later reused as ffn out
__device__ __half g_x1   [NTOK * CCH];
__device__ __half g_h1   [NTOK * DFF];
__device__ __half g_valp [NB * PBATCH * CCH];

__device__ float g_off [NTOK * CCH];
__device__ float g_aw  [NTOK * 128];

__device__ __half g_woffh [CCH * CCH];
__device__ __half g_wattnh[128 * CCH];
__device__ __half g_wvalh [CCH * CCH];
__device__ __half g_wouth [CCH * CCH];
__device__ __half g_w1h   [DFF * CCH];
__device__ __half g_w2h   [CCH * DFF];

// ---------------------------------------------------------------------------
// helpers
// ---------------------------------------------------------------------------
__device__ __forceinline__ unsigned smem_u32(const void* p) {
    unsigned a;
    asm("{ .reg .u64 t; cvta.to.shared.u64 t, %1; cvt.u32.u64 %0, t; }" : "=r"(a) : "l"(p));
    return a;
}

__device__ __forceinline__ void cp_async16(unsigned dst, const void* src) {
    asm volatile("cp.async.cg.shared.global [%0], [%1], 16;\n" :: "r"(dst), "l"(src));
}
__device__ __forceinline__ void cp_commit() {
    asm volatile("cp.async.commit_group;\n" ::: "memory");
}
template<int N>
__device__ __forceinline__ void cp_wait() {
    asm volatile("cp.async.wait_group %0;\n" :: "n"(N) : "memory");
}

__device__ __forceinline__ void ldm4(unsigned& r0, unsigned& r1, unsigned& r2, unsigned& r3,
                                     unsigned a) {
    asm volatile("ldmatrix.sync.aligned.m8n8.x4.shared.b16 {%0,%1,%2,%3}, [%4];"
                 : "=r"(r0), "=r"(r1), "=r"(r2), "=r"(r3) : "r"(a));
}

__device__ __forceinline__ void mma_f16(float c[4],
                                        unsigned a0, unsigned a1, unsigned a2, unsigned a3,
                                        unsigned b0, unsigned b1) {
    asm volatile(
        "mma.sync.aligned.m16n8k16.row.col.f32.f16.f16.f32 "
        "{%0,%1,%2,%3},{%4,%5,%6,%7},{%8,%9},{%0,%1,%2,%3};"
        : "+f"(c[0]), "+f"(c[1]), "+f"(c[2]), "+f"(c[3])
        : "r"(a0), "r"(a1), "r"(a2), "r"(a3), "r"(b0), "r"(b1));
}

// token -> padded value row base (channel 0)
__device__ __forceinline__ __half* valp_row(__half* Vp, int t) {
    int b = t / LEN;
    int pos = t - b * LEN;
    int base, W4, ys, m, loc;
    if (pos < 4096)      { loc = pos;        base = PB0; W4 = 68; ys = 6; m = 63; }
    else if (pos < 5120) { loc = pos - 4096; base = PB1; W4 = 36; ys = 5; m = 31; }
    else if (pos < 5376) { loc = pos - 5120; base = PB2; W4 = 20; ys = 4; m = 15; }
    else                 { loc = pos - 5376; base = PB3; W4 = 12; ys = 3; m = 7; }
    int y = loc >> ys, x = loc & m;
    return Vp + ((size_t)b * PBATCH + base + (y + 2) * W4 + (x + 2)) * CCH;
}

// ===========================================================================
// GEMM variant A (BM=64, BN=128, warp 32x32, NST=4) — ffn2, fp16 out.
// ===========================================================================
#define NST 4
#define GBM 64
#define A_BYTES (GBM * 128)
#define STAGE_SZ ((GBM + 128) * 128)   // 24576

__device__ __forceinline__ void gemm_load_stage(unsigned sb, int stage,
                                                const __half* A, const __half* B,
                                                int K, int kt, int tid) {
    const unsigned abase = sb + stage * STAGE_SZ;
    const unsigned bbase = abase + A_BYTES;
    const __half* ag = A + kt * 64;
    const __half* bg = B + kt * 64;
    #pragma unroll
    for (int i = 0; i < 2; i++) {
        int id = tid + i * 256;
        int r = id >> 3, c = id & 7;
        unsigned off = (unsigned)(r * 128 + ((c ^ (r & 7)) << 4));
        cp_async16(abase + off, ag + (size_t)r * K + c * 8);
    }
    #pragma unroll
    for (int i = 0; i < 4; i++) {
        int id = tid + i * 256;
        int r = id >> 3, c = id & 7;
        unsigned off = (unsigned)(r * 128 + ((c ^ (r & 7)) << 4));
        cp_async16(bbase + off, bg + (size_t)r * K + c * 8);
    }
    cp_commit();
}

__global__ __launch_bounds__(256, 2)
void mma_gemm64(const __half* __restrict__ A, const __half* __restrict__ Bt,
                const float* __restrict__ bias, __half* __restrict__ Ch,
                int N, int K) {
    extern __shared__ __align__(1024) char smem[];
    const unsigned sb = smem_u32(smem);
    const int tid = threadIdx.x;
    const int warp = tid >> 5, lane = tid & 31;
    const int wm = warp & 1, wn = warp >> 1;
    const int bx = blockIdx.x, by = blockIdx.y;
    const __half* Ab = A + (size_t)by * GBM * K;
    const __half* Bb = Bt + (size_t)bx * 128 * (size_t)K;
    const float* biasb = bias + bx * 128;
    __half* Cb = Ch + bx * 128;
    const int KT = K >> 6;

    float acc[2][4][4];
    #pragma unroll
    for (int i = 0; i < 2; i++)
        #pragma unroll
        for (int j = 0; j < 4; j++)
            #pragma unroll
            for (int r = 0; r < 4; r++) acc[i][j][r] = 0.f;

    #pragma unroll
    for (int s = 0; s < NST - 1; s++) {
        if (s < KT) gemm_load_stage(sb, s, Ab, Bb, K, s, tid);
        else        cp_commit();
    }

    const int a_row  = (lane & 15);
    const int a_csel = (lane >> 4);
    const int b_rsel = ((lane >> 4) << 3) + (lane & 7);
    const int b_csel = ((lane >> 3) & 1);

    for (int kt = 0; kt < KT; kt++) {
        const int stage = kt % NST;
        cp_wait<NST - 2>();
        __syncthreads();
        if (kt + NST - 1 < KT)
            gemm_load_stage(sb, (kt + NST - 1) % NST, Ab, Bb, K, kt + NST - 1, tid);
        else
            cp_commit();

        const unsigned ab = sb + stage * STAGE_SZ;
        const unsigned bb = ab + A_BYTES;

        #pragma unroll
        for (int kk = 0; kk < 4; kk++) {
            const int c = kk * 2;
            unsigned af[2][4], bf[2][4];
            #pragma unroll
            for (int mi = 0; mi < 2; mi++) {
                int row = wm * 32 + mi * 16 + a_row;
                unsigned so = (unsigned)(row * 128 + (((c + a_csel) ^ (row & 7)) << 4));
                ldm4(af[mi][0], af[mi][1], af[mi][2], af[mi][3], ab + so);
            }
            #pragma unroll
            for (int nj2 = 0; nj2 < 2; nj2++) {
                int nrow = wn * 32 + nj2 * 16 + b_rsel;
                unsigned so = (unsigned)(nrow * 128 + (((c + b_csel) ^ (nrow & 7)) << 4));
                ldm4(bf[nj2][0], bf[nj2][1], bf[nj2][2], bf[nj2][3], bb + so);
            }
            #pragma unroll
            for (int mi = 0; mi < 2; mi++)
                #pragma unroll
                for (int nj = 0; nj < 4; nj++) {
                    const unsigned* b = bf[nj >> 1];
                    unsigned b0 = (nj & 1) ? b[2] : b[0];
                    unsigned b1 = (nj & 1) ? b[3] : b[1];
                    mma_f16(acc[mi][nj], af[mi][0], af[mi][1], af[mi][2], af[mi][3], b0, b1);
                }
        }
    }

    const int col0 = wn * 32 + (lane & 3) * 2;
    #pragma unroll
    for (int mi = 0; mi < 2; mi++) {
        int row = by * GBM + wm * 32 + mi * 16 + (lane >> 2);
        #pragma unroll
        for (int nj = 0; nj < 4; nj++) {
            int col = col0 + nj * 8;
            float b0v = biasb[col], b1v = biasb[col + 1];
            *(__half2*)(Cb + (size_t)row * N + col) =
                __floats2half2_rn(acc[mi][nj][0] + b0v, acc[mi][nj][1] + b1v);
            *(__half2*)(Cb + (size_t)(row + 8) * N + col) =
                __floats2half2_rn(acc[mi][nj][2] + b0v, acc[mi][nj][3] + b1v);
        }
    }
}

// ===========================================================================
// GEMM variant B (BM=128, BN=128, 8 warps 4m x 2n, warp 32x64, NST=3)
// — proj and ffn1. OUT_MODE 0: fp32; 1: relu+fp16; 2: padded value.
// ===========================================================================
#define NST1 3
#define STAGE1 (256 * 128)   // 32768

__device__ __forceinline__ void load_stage128(unsigned sb, int stage,
                                              const __half* A, const __half* B,
                                              int K, int kt, int tid) {
    const unsigned abase = sb + stage * STAGE1;
    const unsigned bbase = abase + 128 * 128;
    const __half* ag = A + kt * 64;
    const __half* bg = B + kt * 64;
    #pragma unroll
    for (int i = 0; i < 4; i++) {
        int id = tid + i * 256;
        int r = id >> 3, c = id & 7;
        unsigned off = (unsigned)(r * 128 + ((c ^ (r & 7)) << 4));
        cp_async16(abase + off, ag + (size_t)r * K + c * 8);
    }
    #pragma unroll
    for (int i = 0; i < 4; i++) {
        int id = tid + i * 256;
        int r = id >> 3, c = id & 7;
        unsigned off = (unsigned)(r * 128 + ((c ^ (r & 7)) << 4));
        cp_async16(bbase + off, bg + (size_t)r * K + c * 8);
    }
    cp_commit();
}

template<int OUT_MODE>
__device__ __forceinline__ void gemm_body128(const __half* A, const __half* B,
                                             const float* bias, float* Cf, __half* C2,
                                             int N, int K, int row_base, int col_base,
                                             char* smem) {
    const unsigned sb = smem_u32(smem);
    const int tid = threadIdx.x;
    const int warp = tid >> 5, lane = tid & 31;
    const int wm = warp >> 1, wn = warp & 1;   // 4m x 2n
    const int KT = K >> 6;

    float acc[2][8][4];
    #pragma unroll
    for (int i = 0; i < 2; i++)
        #pragma unroll
        for (int j = 0; j < 8; j++)
            #pragma unroll
            for (int r = 0; r < 4; r++) acc[i][j][r] = 0.f;

    #pragma unroll
    for (int s = 0; s < NST1 - 1; s++) {
        if (s < KT) load_stage128(sb, s, A, B, K, s, tid);
        else        cp_commit();
    }

    const int a_row  = (lane & 15);
    const int a_csel = (lane >> 4);
    const int b_rsel = ((lane >> 4) << 3) + (lane & 7);
    const int b_csel = ((lane >> 3) & 1);

    for (int kt = 0; kt < KT; kt++) {
        const int stage = kt % NST1;
        cp_wait<NST1 - 2>();
        __syncthreads();
        if (kt + NST1 - 1 < KT)
            load_stage128(sb, (kt + NST1 - 1) % NST1, A, B, K, kt + NST1 - 1, tid);
        else
            cp_commit();

        const unsigned ab = sb + stage * STAGE1;
        const unsigned bb = ab + 128 * 128;

        #pragma unroll
        for (int kk = 0; kk < 4; kk++) {
            const int c = kk * 2;
            unsigned af[2][4], bf[4][4];
            #pragma unroll
            for (int mi = 0; mi < 2; mi++) {
                int row = wm * 32 + mi * 16 + a_row;
                unsigned so = (unsigned)(row * 128 + (((c + a_csel) ^ (row & 7)) << 4));
                ldm4(af[mi][0], af[mi][1], af[mi][2], af[mi][3], ab + so);
            }
            #pragma unroll
            for (int nj2 = 0; nj2 < 4; nj2++) {
                int nrow = wn * 64 + nj2 * 16 + b_rsel;
                unsigned so = (unsigned)(nrow * 128 + (((c + b_csel) ^ (nrow & 7)) << 4));
                ldm4(bf[nj2][0], bf[nj2][1], bf[nj2][2], bf[nj2][3], bb + so);
            }
            #pragma unroll
            for (int mi = 0; mi < 2; mi++)
                #pragma unroll
                for (int nj = 0; nj < 8; nj++) {
                    const unsigned* b = bf[nj >> 1];
                    unsigned b0 = (nj & 1) ? b[2] : b[0];
                    unsigned b1 = (nj & 1) ? b[3] : b[1];
                    mma_f16(acc[mi][nj], af[mi][0], af[mi][1], af[mi][2], af[mi][3], b0, b1);
                }
        }
    }

    const int col0 = wn * 64 + (lane & 3) * 2;
    #pragma unroll
    for (int mi = 0; mi < 2; mi++) {
        int row = row_base + wm * 32 + mi * 16 + (lane >> 2);
        __half *p0 = nullptr, *p1 = nullptr;
        if (OUT_MODE == 2) {
            p0 = valp_row(C2, row) + col_base;
            p1 = valp_row(C2, row + 8) + col_base;
        }
        #pragma unroll
        for (int nj = 0; nj < 8; nj++) {
            int col = col0 + nj * 8;
            float b0v = bias[col], b1v = bias[col + 1];
            float v00 = acc[mi][nj][0] + b0v, v01 = acc[mi][nj][1] + b1v;
            float v10 = acc[mi][nj][2] + b0v, v11 = acc[mi][nj][3] + b1v;
            if (OUT_MODE == 0) {
                *(float2*)(Cf + (size_t)row * N + col)       = make_float2(v00, v01);
                *(float2*)(Cf + (size_t)(row + 8) * N + col) = make_float2(v10, v11);
            } else if (OUT_MODE == 1) {
                v00 = fmaxf(v00, 0.f); v01 = fmaxf(v01, 0.f);
                v10 = fmaxf(v10, 0.f); v11 = fmaxf(v11, 0.f);
                *(__half2*)(C2 + (size_t)row * N + col)       = __floats2half2_rn(v00, v01);
                *(__half2*)(C2 + (size_t)(row + 8) * N + col) = __floats2half2_rn(v10, v11);
            } else {
                *(__half2*)(p0 + col) = __floats2half2_rn(v00, v01);
                *(__half2*)(p1 + col) = __floats2half2_rn(v10, v11);
            }
        }
    }
}

// ffn1 GEMM: BM=128, relu + fp16 out
__global__ __launch_bounds__(256, 2)
void ffn1_gemm(const __half* __restrict__ A, const __half* __restrict__ Bt,
               const float* __restrict__ bias, __half* __restrict__ C2,
               int N, int K) {
    extern __shared__ __align__(1024) char smem[];
    const int bx = blockIdx.x, by = blockIdx.y;
    gemm_body128<1>(A + (size_t)by * 128 * K,
                    Bt + (size_t)bx * 128 * (size_t)K,
                    bias + bx * 128, nullptr, C2 + bx * 128,
                    N, K, by * 128, 0, smem);
}

// fused projection GEMM (BM=128): bx selects {off0, off1, logits, val0, val1}
__global__ __launch_bounds__(256, 2)
void proj_gemm(const __half* __restrict__ q1, const __half* __restrict__ src1,
               const __half* __restrict__ woffh, const __half* __restrict__ wattnh,
               const __half* __restrict__ wvalh,
               const float* __restrict__ b_off, const float* __restrict__ b_attn,
               const float* __restrict__ b_val,
               float* __restrict__ c_off, float* __restrict__ c_aw,
               __half* __restrict__ valp) {
    extern __shared__ __align__(1024) char smem[];
    const int bx = blockIdx.x, by = blockIdx.y;
    const int K = CCH;

    if (bx < 2) {
        gemm_body128<0>(q1 + (size_t)by * 128 * K, woffh + (size_t)bx * 128 * K,
                        b_off + bx * 128, c_off + bx * 128, nullptr,
                        CCH, K, by * 128, 0, smem);
    } else if (bx == 2) {
        gemm_body128<0>(q1 + (size_t)by * 128 * K, wattnh,
                        b_attn, c_aw, nullptr,
                        128, K, by * 128, 0, smem);
    } else {
        int s = bx - 3;
        gemm_body128<2>(src1 + (size_t)by * 128 * K, wvalh + (size_t)s * 128 * K,
                        b_val + s * 128, nullptr, valp,
                        CCH, K, by * 128, s * 128, smem);
    }
}

// ---------------------------------------------------------------------------
// Fused attn GEMM(BM=32, BN=256) + residual(src fp32) + LN1 -> x1 fp16 only.
// ---------------------------------------------------------------------------
#define ALN_STAGE ((32 + 256) * 128)        // 36864
#define ALN_CSTR 264
#define ALN_SMEM (2 * ALN_STAGE + 32 * ALN_CSTR * 4)   // 107520

__global__ __launch_bounds__(256, 2)
void attn_ln_gemm(const __half* __restrict__ A, const __half* __restrict__ Bt,
                  const float* __restrict__ bias, const float* __restrict__ src,
                  const float* __restrict__ g1, const float* __restrict__ be1,
                  __half* __restrict__ x1out) {
    extern __shared__ __align__(1024) char smem[];
    const unsigned sb = smem_u32(smem);
    float* cbuf = (float*)(smem + 2 * ALN_STAGE);
    const int tid = threadIdx.x;
    const int warp = tid >> 5, lane = tid & 31;
    const int row0 = blockIdx.x * 32;
    const int K = CCH;
    const int KT = 4;

    float acc[2][4][4];
    #pragma unroll
    for (int i = 0; i < 2; i++)
        #pragma unroll
        for (int j = 0; j < 4; j++)
            #pragma unroll
            for (int r = 0; r < 4; r++) acc[i][j][r] = 0.f;

    {
        const unsigned abase = sb;
        const unsigned bbase = sb + 32 * 128;
        const __half* ag = A + (size_t)row0 * K;
        {
            int r = tid >> 3, c = tid & 7;
            unsigned off = (unsigned)(r * 128 + ((c ^ (r & 7)) << 4));
            cp_async16(abase + off, ag + (size_t)r * K + c * 8);
        }
        #pragma unroll
        for (int i = 0; i < 8; i++) {
            int id = tid + i * 256;
            int r = id >> 3, c = id & 7;
            unsigned off = (unsigned)(r * 128 + ((c ^ (r & 7)) << 4));
            cp_async16(bbase + off, Bt + (size_t)r * K + c * 8);
        }
        cp_commit();
    }

    const int a_row  = (lane & 15);
    const int a_csel = (lane >> 4);
    const int b_rsel = ((lane >> 4) << 3) + (lane & 7);
    const int b_csel = ((lane >> 3) & 1);

    for (int kt = 0; kt < KT; kt++) {
        const int stage = kt & 1;
        cp_wait<0>();
        __syncthreads();
        if (kt + 1 < KT) {
            const unsigned abase = sb + (stage ^ 1) * ALN_STAGE;
            const unsigned bbase = abase + 32 * 128;
            const __half* ag = A + (size_t)row0 * K + (kt + 1) * 64;
            const __half* bg = Bt + (kt + 1) * 64;
            {
                int r = tid >> 3, c = tid & 7;
                unsigned off = (unsigned)(r * 128 + ((c ^ (r & 7)) << 4));
                cp_async16(abase + off, ag + (size_t)r * K + c * 8);
            }
            #pragma unroll
            for (int i = 0; i < 8; i++) {
                int id = tid + i * 256;
                int r = id >> 3, c = id & 7;
                unsigned off = (unsigned)(r * 128 + ((c ^ (r & 7)) << 4));
                cp_async16(bbase + off, bg + (size_t)r * K + c * 8);
            }
            cp_commit();
        }

        const unsigned ab = sb + stage * ALN_STAGE;
        const unsigned bb = ab + 32 * 128;

        #pragma unroll
        for (int kk = 0; kk < 4; kk++) {
            const int c = kk * 2;
            unsigned af[2][4], bf[2][4];
            #pragma unroll
            for (int mi = 0; mi < 2; mi++) {
                int row = mi * 16 + a_row;
                unsigned so = (unsigned)(row * 128 + (((c + a_csel) ^ (row & 7)) << 4));
                ldm4(af[mi][0], af[mi][1], af[mi][2], af[mi][3], ab + so);
            }
            #pragma unroll
            for (int nj2 = 0; nj2 < 2; nj2++) {
                int nrow = warp * 32 + nj2 * 16 + b_rsel;
                unsigned so = (unsigned)(nrow * 128 + (((c + b_csel) ^ (nrow & 7)) << 4));
                ldm4(bf[nj2][0], bf[nj2][1], bf[nj2][2], bf[nj2][3], bb + so);
            }
            #pragma unroll
            for (int mi = 0; mi < 2; mi++)
                #pragma unroll
                for (int nj = 0; nj < 4; nj++) {
                    const unsigned* b = bf[nj >> 1];
                    unsigned b0 = (nj & 1) ? b[2] : b[0];
                    unsigned b1 = (nj & 1) ? b[3] : b[1];
                    mma_f16(acc[mi][nj], af[mi][0], af[mi][1], af[mi][2], af[mi][3], b0, b1);
                }
        }
    }

    const int colw = warp * 32 + (lane & 3) * 2;
    #pragma unroll
    for (int mi = 0; mi < 2; mi++) {
        int r = mi * 16 + (lane >> 2);
        #pragma unroll
        for (int nj = 0; nj < 4; nj++) {
            int col = colw + nj * 8;
            float b0v = bias[col], b1v = bias[col + 1];
            cbuf[r * ALN_CSTR + col]           = acc[mi][nj][0] + b0v;
            cbuf[r * ALN_CSTR + col + 1]       = acc[mi][nj][1] + b1v;
            cbuf[(r + 8) * ALN_CSTR + col]     = acc[mi][nj][2] + b0v;
            cbuf[(r + 8) * ALN_CSTR + col + 1] = acc[mi][nj][3] + b1v;
        }
    }
    __syncthreads();

    #pragma unroll
    for (int rr = 0; rr < 4; rr++) {
        const int r = warp * 4 + rr;
        const size_t grow = (size_t)(row0 + r);
        float v[8];
        float s = 0.f;
        #pragma unroll
        for (int j = 0; j < 8; j++) {
            int c = lane + 32 * j;
            v[j] = cbuf[r * ALN_CSTR + c] + src[grow * CCH + c];
            s += v[j];
        }
        #pragma unroll
        for (int o = 16; o > 0; o >>= 1) s += __shfl_xor_sync(0xffffffffu, s, o);
        const float mean = s * (1.f / CCH);
        float s2 = 0.f;
        #pragma unroll
        for (int j = 0; j < 8; j++) { float d = v[j] - mean; s2 += d * d; }
        #pragma unroll
        for (int o = 16; o > 0; o >>= 1) s2 += __shfl_xor_sync(0xffffffffu, s2, o);
        const float inv = rsqrtf(s2 * (1.f / CCH) + LN_EPS);
        #pragma unroll
        for (int j = 0; j < 8; j++) {
            int c = lane + 32 * j;
            float y = (v[j] - mean) * inv * g1[c] + be1[c];
            x1out[grow * CCH + c] = __float2half_rn(y);
        }
    }
}

// ---------------------------------------------------------------------------
// merged prep: act conversion + border zero + weight transposes, one launch.
// ---------------------------------------------------------------------------
__global__ void prep_kernel(const float* __restrict__ src, const float* __restrict__ pos,
                            __half* __restrict__ q1, __half* __restrict__ s1,
                            __half* __restrict__ valp,
                            const float* __restrict__ w_off, const float* __restrict__ w_attn,
                            const float* __restrict__ w_val, const float* __restrict__ w_out,
                            const float* __restrict__ w1,    const float* __restrict__ w2,
                            __half* __restrict__ d_off, __half* __restrict__ d_attn,
                            __half* __restrict__ d_val, __half* __restrict__ d_out,
                            __half* __restrict__ d_w1,  __half* __restrict__ d_w2) {
    __shared__ float tile[32][33];
    const int bid = blockIdx.x;
    const int tid = threadIdx.x;

    if (bid < 10880) {
        int i = bid * 256 + tid;
        float2 s = ((const float2*)src)[i];
        float2 p = ((const float2*)pos)[i];
        ((__half2*)s1)[i] = __floats2half2_rn(s.x, s.y);
        ((__half2*)q1)[i] = __floats2half2_rn(s.x + p.x, s.y + p.y);
    } else if (bid < 14112) {
        const int gid = (bid - 10880) * 8 + (tid >> 5);
        const int lane = tid & 31;
        int cell = gid % PBATCH;
        int W4, loc;
        if (cell < PB1)      { loc = cell;       W4 = 68; }
        else if (cell < PB2) { loc = cell - PB1; W4 = 36; }
        else if (cell < PB3) { loc = cell - PB2; W4 = 20; }
        else                 { loc = cell - PB3; W4 = 12; }
        const int y = loc / W4, x = loc - y * W4;
        if ((y < 2) | (y >= W4 - 2) | (x < 2) | (x >= W4 - 2)) {
            uint4* p = (uint4*)(valp + (size_t)gid * CCH);
            p[lane] = make_uint4(0u, 0u, 0u, 0u);
        }
    } else {
        int id = bid - 14112;
        const float* W; __half* Bt; int K, N, nx, local;
        if      (id < 64)  { W = w_off;  Bt = d_off;  K = CCH; N = CCH; nx = 8;  local = id; }
        else if (id < 96)  { W = w_attn; Bt = d_attn; K = CCH; N = 128; nx = 4;  local = id - 64; }
        else if (id < 160) { W = w_val;  Bt = d_val;  K = CCH; N = CCH; nx = 8;  local = id - 96; }
        else if (id < 224) { W = w_out;  Bt = d_out;  K = CCH; N = CCH; nx = 8;  local = id - 160; }
        else if (id < 480) { W = w1;     Bt = d_w1;   K = CCH; N = DFF; nx = 32; local = id - 224; }
        else               { W = w2;     Bt = d_w2;   K = DFF; N = CCH; nx = 8;  local = id - 480; }
        const int n0 = (local % nx) * 32, k0 = (local / nx) * 32;
        const int tx = tid & 31, ty = tid >> 5;
        #pragma unroll
        for (int i = 0; i < 4; i++) {
            int k = ty + i * 8;
            tile[k][tx] = W[(size_t)(k0 + k) * N + n0 + tx];
        }
        __syncthreads();
        #pragma unroll
        for (int i = 0; i < 4; i++) {
            int n = ty + i * 8;
            Bt[(size_t)(n0 + n) * K + k0 + tx] = __float2half_rn(tile[tx][n]);
        }
    }
}

// ---------------------------------------------------------------------------
// MSDA: half2 channels, one warp serves two heads.
// ---------------------------------------------------------------------------
__global__ void msda_kernel(const __half* __restrict__ valp,
                            const float* __restrict__ off,
                            const float* __restrict__ logits,
                            const float* __restrict__ refp,
                            __half* __restrict__ out1) {
    const int warp = threadIdx.x >> 5;
    const int lane = threadIdx.x & 31;
    const int hp = warp & 3;
    const int t  = blockIdx.x * 2 + (warp >> 2);
    const int b  = t / LEN;
    const int p  = lane & 15;
    const int h  = hp * 2 + (lane >> 4);
    const int hsel = lane & 16;

    const float* lg = logits + (size_t)t * 128 + h * 16;
    float l0 = lg[p];
    float mx = l0;
    #pragma unroll
    for (int o = 1; o < 16; o <<= 1) mx = fmaxf(mx, __shfl_xor_sync(0xffffffffu, mx, o));
    float e = __expf(l0 - mx);
    float s = e;
    #pragma unroll
    for (int o = 1; o < 16; o <<= 1) s += __shfl_xor_sync(0xffffffffu, s, o);
    const float wgt = e / s;

    const int l  = p >> 2;
    const int Wl = 64 >> l;
    const int W4 = Wl + 4;
    const int base = (l == 0) ? PB0 : (l == 1) ? PB1 : (l == 2) ? PB2 : PB3;
    const float2* off2 = (const float2*)(off + (size_t)t * CCH + h * (NL * NP * 2));
    const float2* ref2 = (const float2*)(refp + (size_t)t * (NL * 2));
    float2 o2 = off2[p];
    float2 r2 = ref2[l];
    const float fW = (float)Wl;
    const float px = fmaf(r2.x, fW, o2.x - 0.5f);
    const float py = fmaf(r2.y, fW, o2.y - 0.5f);
    const float fx = floorf(px), fy = floorf(py);
    const int x0 = (int)fx, y0 = (int)fy;
    const float wx1 = px - fx, wy1 = py - fy;
    const float wx0 = 1.f - wx1, wy0 = 1.f - wy1;
    const int x0c = min(max(x0, -2), Wl);
    const int y0c = min(max(y0, -2), Wl);
    const int rcell = base + (y0c + 2) * W4 + (x0c + 2);
    const float w00 = wgt * wx0 * wy0;
    const float w10 = wgt * wx1 * wy0;
    const float w01 = wgt * wx0 * wy1;
    const float w11 = wgt * wx1 * wy1;

    const __half* vbase = valp + ((size_t)b * PBATCH) * CCH + h * DH + p * 2;
    float accx = 0.f, accy = 0.f;

    #pragma unroll
    for (int q = 0; q < 16; q++) {
        const int W4q = (64 >> (q >> 2)) + 4;
        const int src = q | hsel;
        const int rc  = __shfl_sync(0xffffffffu, rcell, src);
        const float a00 = __shfl_sync(0xffffffffu, w00, src);
        const float a10 = __shfl_sync(0xffffffffu, w10, src);
        const float a01 = __shfl_sync(0xffffffffu, w01, src);
        const float a11 = __shfl_sync(0xffffffffu, w11, src);
        const __half* qp = vbase + (size_t)rc * CCH;
        float2 v00 = __half22float2(*(const __half2*)(qp));
        float2 v10 = __half22float2(*(const __half2*)(qp + CCH));
        float2 v01 = __half22float2(*(const __half2*)(qp + (size_t)W4q * CCH));
        float2 v11 = __half22float2(*(const __half2*)(qp + (size_t)(W4q + 1) * CCH));
        accx = fmaf(a00, v00.x, accx); accy = fmaf(a00, v00.y, accy);
        accx = fmaf(a10, v10.x, accx); accy = fmaf(a10, v10.y, accy);
        accx = fmaf(a01, v01.x, accx); accy = fmaf(a01, v01.y, accy);
        accx = fmaf(a11, v11.x, accx); accy = fmaf(a11, v11.y, accy);
    }
    *(__half2*)(out1 + (size_t)t * CCH + h * DH + p * 2) = __floats2half2_rn(accx, accy);
}

// ---------------------------------------------------------------------------
// Final LN2: out = LN(x1 + ffn), both fp16 inputs, half2-vectorized.
// warp per row.
// ---------------------------------------------------------------------------
__global__ void ln2_kernel(const __half* __restrict__ a, const __half* __restrict__ b,
                           const float* __restrict__ g, const float* __restrict__ be,
                           float* __restrict__ out, int rows) {
    const int row = blockIdx.x * (blockDim.x >> 5) + (threadIdx.x >> 5);
    const int lane = threadIdx.x & 31;
    if (row >= rows) return;

    const __half2* pa = (const __half2*)(a + (size_t)row * CCH);
    const __half2* pb = (const __half2*)(b + (size_t)row * CCH);
    float2 v[4];
    float s = 0.f;
    #pragma unroll
    for (int j = 0; j < 4; j++) {
        int c = lane + 32 * j;
        float2 va = __half22float2(pa[c]);
        float2 vb = __half22float2(pb[c]);
        v[j].x = va.x + vb.x;
        v[j].y = va.y + vb.y;
        s += v[j].x + v[j].y;
    }
    #pragma unroll
    for (int o = 16; o > 0; o >>= 1) s += __shfl_xor_sync(0xffffffffu, s, o);
    const float mean = s * (1.f / CCH);
    float s2 = 0.f;
    #pragma unroll
    for (int j = 0; j < 4; j++) {
        float dx = v[j].x - mean, dy = v[j].y - mean;
        s2 += dx * dx + dy * dy;
    }
    #pragma unroll
    for (int o = 16; o > 0; o >>= 1) s2 += __shfl_xor_sync(0xffffffffu, s2, o);
    const float inv = rsqrtf(s2 * (1.f / CCH) + LN_EPS);

    float* po = out + (size_t)row * CCH;
    #pragma unroll
    for (int j = 0; j < 4; j++) {
        int c = lane + 32 * j;
        float y0 = (v[j].x - mean) * inv * g[2 * c]     + be[2 * c];
        float y1 = (v[j].y - mean) * inv * g[2 * c + 1] + be[2 * c + 1];
        *(float2*)(po + 2 * c) = make_float2(y0, y1);
    }
}

// ---------------------------------------------------------------------------
// launch
// ---------------------------------------------------------------------------
extern "C" void kernel_launch(void* const* d_in, const int* in_sizes, int n_in,
                              void* d_out, int out_size) {
    const float* src   = (const float*)d_in[0];
    const float* pos   = (const float*)d_in[1];
    const float* refp  = (const float*)d_in[2];
    const float* w_off  = (const float*)d_in[6];
    const float* b_off  = (const float*)d_in[7];
    const float* w_attn = (const float*)d_in[8];
    const float* b_attn = (const float*)d_in[9];
    const float* w_val  = (const float*)d_in[10];
    const float* b_val  = (const float*)d_in[11];
    const float* w_out  = (const float*)d_in[12];
    const float* b_out  = (const float*)d_in[13];
    const float* g1     = (const float*)d_in[14];
    const float* be1    = (const float*)d_in[15];
    const float* w1     = (const float*)d_in[16];
    const float* b1     = (const float*)d_in[17];
    const float* w2     = (const float*)d_in[18];
    const float* b2     = (const float*)d_in[19];
    const float* g2     = (const float*)d_in[20];
    const float* be2    = (const float*)d_in[21];
    float* out = (float*)d_out;

    __half *p_q1, *p_src1, *p_msda1, *p_x1, *p_h1, *p_valp;
    __half *p_woffh, *p_wattnh, *p_wvalh, *p_wouth, *p_w1h, *p_w2h;
    float *p_off, *p_aw;
    cudaGetSymbolAddress((void**)&p_q1,    g_q1);
    cudaGetSymbolAddress((void**)&p_src1,  g_src1);
    cudaGetSymbolAddress((void**)&p_msda1, g_msda1);
    cudaGetSymbolAddress((void**)&p_x1,    g_x1);
    cudaGetSymbolAddress((void**)&p_h1,    g_h1);
    cudaGetSymbolAddress((void**)&p_valp,  g_valp);
    cudaGetSymbolAddress((void**)&p_woffh, g_woffh);
    cudaGetSymbolAddress((void**)&p_wattnh,g_wattnh);
    cudaGetSymbolAddress((void**)&p_wvalh, g_wvalh);
    cudaGetSymbolAddress((void**)&p_wouth, g_wouth);
    cudaGetSymbolAddress((void**)&p_w1h,   g_w1h);
    cudaGetSymbolAddress((void**)&p_w2h,   g_w2h);
    cudaGetSymbolAddress((void**)&p_off,   g_off);
    cudaGetSymbolAddress((void**)&p_aw,    g_aw);

    const int M = NTOK;  // 21760 = 170 * 128 = 340 * 64 = 680 * 32
    const dim3 blk(256);

    const int SM_A = NST  * STAGE_SZ;   // 98304
    const int SM_B = NST1 * STAGE1;     // 98304
    cudaFuncSetAttribute(proj_gemm,    cudaFuncAttributeMaxDynamicSharedMemorySize, SM_B);
    cudaFuncSetAttribute(ffn1_gemm,    cudaFuncAttributeMaxDynamicSharedMemorySize, SM_B);
    cudaFuncSetAttribute(mma_gemm64,   cudaFuncAttributeMaxDynamicSharedMemorySize, SM_A);
    cudaFuncSetAttribute(attn_ln_gemm, cudaFuncAttributeMaxDynamicSharedMemorySize, ALN_SMEM);

    // merged prep: act conversion + border zero + weight transposes
    prep_kernel<<<14848, blk>>>(src, pos, p_q1, p_src1, p_valp,
                                w_off, w_attn, w_val, w_out, w1, w2,
                                p_woffh, p_wattnh, p_wvalh, p_wouth, p_w1h, p_w2h);

    // fused projections (BM=128): off / logits / value(padded fp16)
    proj_gemm<<<dim3(5, M / 128), blk, SM_B>>>(p_q1, p_src1, p_woffh, p_wattnh, p_wvalh,
                                               b_off, b_attn, b_val, p_off, p_aw, p_valp);
    // MSDA gather (softmax fused, half2 channels, 2 heads per warp)
    msda_kernel<<<NTOK / 2, blk>>>(p_valp, p_off, p_aw, refp, p_msda1);
    // attn_out GEMM + residual(src) + LN1 -> x1 fp16
    attn_ln_gemm<<<M / 32, blk, ALN_SMEM>>>(p_msda1, p_wouth, b_out, src, g1, be1, p_x1);
    // h = relu(x1 @ w1 + b1) -> fp16 (BM=128)
    ffn1_gemm<<<dim3(8, M / 128), blk, SM_B>>>(p_x1, p_w1h, b1, p_h1, DFF, CCH);
    // ffn = h @ w2 + b2 -> fp16 (reuse msda buffer)
    mma_gemm64<<<dim3(2, M / 64), blk, SM_A>>>(p_h1, p_w2h, b2, p_msda1, CCH, DFF);
    // out = LN(x1 + ffn), fp16 inputs
    ln2_kernel<<<(NTOK + 7) / 8, blk>>>(p_x1, p_msda1, g2, be2, out, NTOK);
}

// round 17
// speedup vs baseline: 1.0582x; 1.0068x over previous
#include <cuda_runtime.h>
#include <cuda_fp16.h>
#include <math.h>

// Problem constants
#define NB   4
#define LEN  5440
#define NTOK (NB * LEN)          // 21760
#define CCH  256
#define NH   8
#define DH   32
#define NL   4
#define NP   4
#define DFF  1024
#define LN_EPS 1e-5f

// Padded value layout: per level pad 2 on all sides, fp16.
#define PBATCH 6464
#define PB0 0
#define PB1 4624
#define PB2 5920
#define PB3 6320

// ---------------------------------------------------------------------------
// Scratch
// ---------------------------------------------------------------------------
__device__ __half g_q1   [NTOK * CCH];
__device__ __half g_src1 [NTOK * CCH];
__device__ __half g_msda1[NTOK * CCH];    // msda out; later reused as ffn out
__device__ __half g_x1   [NTOK * CCH];
__device__ __half g_h1   [NTOK * DFF];
__device__ __half g_valp [NB * PBATCH * CCH];

__device__ float g_off [NTOK * CCH];
__device__ float g_aw  [NTOK * 128];

__device__ __half g_woffh [CCH * CCH];
__device__ __half g_wattnh[128 * CCH];
__device__ __half g_wvalh [CCH * CCH];
__device__ __half g_wouth [CCH * CCH];
__device__ __half g_w1h   [DFF * CCH];
__device__ __half g_w2h   [CCH * DFF];

// ---------------------------------------------------------------------------
// helpers
// ---------------------------------------------------------------------------
__device__ __forceinline__ unsigned smem_u32(const void* p) {
    unsigned a;
    asm("{ .reg .u64 t; cvta.to.shared.u64 t, %1; cvt.u32.u64 %0, t; }" : "=r"(a) : "l"(p));
    return a;
}

__device__ __forceinline__ void cp_async16(unsigned dst, const void* src) {
    asm volatile("cp.async.cg.shared.global [%0], [%1], 16;\n" :: "r"(dst), "l"(src));
}
__device__ __forceinline__ void cp_commit() {
    asm volatile("cp.async.commit_group;\n" ::: "memory");
}
template<int N>
__device__ __forceinline__ void cp_wait() {
    asm volatile("cp.async.wait_group %0;\n" :: "n"(N) : "memory");
}

__device__ __forceinline__ void ldm4(unsigned& r0, unsigned& r1, unsigned& r2, unsigned& r3,
                                     unsigned a) {
    asm volatile("ldmatrix.sync.aligned.m8n8.x4.shared.b16 {%0,%1,%2,%3}, [%4];"
                 : "=r"(r0), "=r"(r1), "=r"(r2), "=r"(r3) : "r"(a));
}

__device__ __forceinline__ void mma_f16(float c[4],
                                        unsigned a0, unsigned a1, unsigned a2, unsigned a3,
                                        unsigned b0, unsigned b1) {
    asm volatile(
        "mma.sync.aligned.m16n8k16.row.col.f32.f16.f16.f32 "
        "{%0,%1,%2,%3},{%4,%5,%6,%7},{%8,%9},{%0,%1,%2,%3};"
        : "+f"(c[0]), "+f"(c[1]), "+f"(c[2]), "+f"(c[3])
        : "r"(a0), "r"(a1), "r"(a2), "r"(a3), "r"(b0), "r"(b1));
}

// token -> padded value row base (channel 0)
__device__ __forceinline__ __half* valp_row(__half* Vp, int t) {
    int b = t / LEN;
    int pos = t - b * LEN;
    int base, W4, ys, m, loc;
    if (pos < 4096)      { loc = pos;        base = PB0; W4 = 68; ys = 6; m = 63; }
    else if (pos < 5120) { loc = pos - 4096; base = PB1; W4 = 36; ys = 5; m = 31; }
    else if (pos < 5376) { loc = pos - 5120; base = PB2; W4 = 20; ys = 4; m = 15; }
    else                 { loc = pos - 5376; base = PB3; W4 = 12; ys = 3; m = 7; }
    int y = loc >> ys, x = loc & m;
    return Vp + ((size_t)b * PBATCH + base + (y + 2) * W4 + (x + 2)) * CCH;
}

// ===========================================================================
// GEMM variant A (BM=64, BN=128, warp 32x32, NST=4) — ffn2, fp16 out.
// ===========================================================================
#define NST 4
#define GBM 64
#define A_BYTES (GBM * 128)
#define STAGE_SZ ((GBM + 128) * 128)   // 24576

__device__ __forceinline__ void gemm_load_stage(unsigned sb, int stage,
                                                const __half* A, const __half* B,
                                                int K, int kt, int tid) {
    const unsigned abase = sb + stage * STAGE_SZ;
    const unsigned bbase = abase + A_BYTES;
    const __half* ag = A + kt * 64;
    const __half* bg = B + kt * 64;
    #pragma unroll
    for (int i = 0; i < 2; i++) {
        int id = tid + i * 256;
        int r = id >> 3, c = id & 7;
        unsigned off = (unsigned)(r * 128 + ((c ^ (r & 7)) << 4));
        cp_async16(abase + off, ag + (size_t)r * K + c * 8);
    }
    #pragma unroll
    for (int i = 0; i < 4; i++) {
        int id = tid + i * 256;
        int r = id >> 3, c = id & 7;
        unsigned off = (unsigned)(r * 128 + ((c ^ (r & 7)) << 4));
        cp_async16(bbase + off, bg + (size_t)r * K + c * 8);
    }
    cp_commit();
}

__global__ __launch_bounds__(256, 2)
void mma_gemm64(const __half* __restrict__ A, const __half* __restrict__ Bt,
                const float* __restrict__ bias, __half* __restrict__ Ch,
                int N, int K) {
    extern __shared__ __align__(1024) char smem[];
    const unsigned sb = smem_u32(smem);
    const int tid = threadIdx.x;
    const int warp = tid >> 5, lane = tid & 31;
    const int wm = warp & 1, wn = warp >> 1;
    const int bx = blockIdx.x, by = blockIdx.y;
    const __half* Ab = A + (size_t)by * GBM * K;
    const __half* Bb = Bt + (size_t)bx * 128 * (size_t)K;
    const float* biasb = bias + bx * 128;
    __half* Cb = Ch + bx * 128;
    const int KT = K >> 6;

    float acc[2][4][4];
    #pragma unroll
    for (int i = 0; i < 2; i++)
        #pragma unroll
        for (int j = 0; j < 4; j++)
            #pragma unroll
            for (int r = 0; r < 4; r++) acc[i][j][r] = 0.f;

    #pragma unroll
    for (int s = 0; s < NST - 1; s++) {
        if (s < KT) gemm_load_stage(sb, s, Ab, Bb, K, s, tid);
        else        cp_commit();
    }

    const int a_row  = (lane & 15);
    const int a_csel = (lane >> 4);
    const int b_rsel = ((lane >> 4) << 3) + (lane & 7);
    const int b_csel = ((lane >> 3) & 1);

    for (int kt = 0; kt < KT; kt++) {
        const int stage = kt % NST;
        cp_wait<NST - 2>();
        __syncthreads();
        if (kt + NST - 1 < KT)
            gemm_load_stage(sb, (kt + NST - 1) % NST, Ab, Bb, K, kt + NST - 1, tid);
        else
            cp_commit();

        const unsigned ab = sb + stage * STAGE_SZ;
        const unsigned bb = ab + A_BYTES;

        #pragma unroll
        for (int kk = 0; kk < 4; kk++) {
            const int c = kk * 2;
            unsigned af[2][4], bf[2][4];
            #pragma unroll
            for (int mi = 0; mi < 2; mi++) {
                int row = wm * 32 + mi * 16 + a_row;
                unsigned so = (unsigned)(row * 128 + (((c + a_csel) ^ (row & 7)) << 4));
                ldm4(af[mi][0], af[mi][1], af[mi][2], af[mi][3], ab + so);
            }
            #pragma unroll
            for (int nj2 = 0; nj2 < 2; nj2++) {
                int nrow = wn * 32 + nj2 * 16 + b_rsel;
                unsigned so = (unsigned)(nrow * 128 + (((c + b_csel) ^ (nrow & 7)) << 4));
                ldm4(bf[nj2][0], bf[nj2][1], bf[nj2][2], bf[nj2][3], bb + so);
            }
            #pragma unroll
            for (int mi = 0; mi < 2; mi++)
                #pragma unroll
                for (int nj = 0; nj < 4; nj++) {
                    const unsigned* b = bf[nj >> 1];
                    unsigned b0 = (nj & 1) ? b[2] : b[0];
                    unsigned b1 = (nj & 1) ? b[3] : b[1];
                    mma_f16(acc[mi][nj], af[mi][0], af[mi][1], af[mi][2], af[mi][3], b0, b1);
                }
        }
    }

    const int col0 = wn * 32 + (lane & 3) * 2;
    #pragma unroll
    for (int mi = 0; mi < 2; mi++) {
        int row = by * GBM + wm * 32 + mi * 16 + (lane >> 2);
        #pragma unroll
        for (int nj = 0; nj < 4; nj++) {
            int col = col0 + nj * 8;
            float b0v = biasb[col], b1v = biasb[col + 1];
            *(__half2*)(Cb + (size_t)row * N + col) =
                __floats2half2_rn(acc[mi][nj][0] + b0v, acc[mi][nj][1] + b1v);
            *(__half2*)(Cb + (size_t)(row + 8) * N + col) =
                __floats2half2_rn(acc[mi][nj][2] + b0v, acc[mi][nj][3] + b1v);
        }
    }
}

// ===========================================================================
// GEMM variant B (BM=128, BN=128, 8 warps 4m x 2n, warp 32x64, NST=3)
// — proj and ffn1. OUT_MODE 0: fp32; 1: relu+fp16; 2: padded value.
// ===========================================================================
#define NST1 3
#define STAGE1 (256 * 128)   // 32768

__device__ __forceinline__ void load_stage128(unsigned sb, int stage,
                                              const __half* A, const __half* B,
                                              int K, int kt, int tid) {
    const unsigned abase = sb + stage * STAGE1;
    const unsigned bbase = abase + 128 * 128;
    const __half* ag = A + kt * 64;
    const __half* bg = B + kt * 64;
    #pragma unroll
    for (int i = 0; i < 4; i++) {
        int id = tid + i * 256;
        int r = id >> 3, c = id & 7;
        unsigned off = (unsigned)(r * 128 + ((c ^ (r & 7)) << 4));
        cp_async16(abase + off, ag + (size_t)r * K + c * 8);
    }
    #pragma unroll
    for (int i = 0; i < 4; i++) {
        int id = tid + i * 256;
        int r = id >> 3, c = id & 7;
        unsigned off = (unsigned)(r * 128 + ((c ^ (r & 7)) << 4));
        cp_async16(bbase + off, bg + (size_t)r * K + c * 8);
    }
    cp_commit();
}

template<int OUT_MODE>
__device__ __forceinline__ void gemm_body128(const __half* A, const __half* B,
                                             const float* bias, float* Cf, __half* C2,
                                             int N, int K, int row_base, int col_base,
                                             char* smem) {
    const unsigned sb = smem_u32(smem);
    const int tid = threadIdx.x;
    const int warp = tid >> 5, lane = tid & 31;
    const int wm = warp >> 1, wn = warp & 1;   // 4m x 2n
    const int KT = K >> 6;

    float acc[2][8][4];
    #pragma unroll
    for (int i = 0; i < 2; i++)
        #pragma unroll
        for (int j = 0; j < 8; j++)
            #pragma unroll
            for (int r = 0; r < 4; r++) acc[i][j][r] = 0.f;

    #pragma unroll
    for (int s = 0; s < NST1 - 1; s++) {
        if (s < KT) load_stage128(sb, s, A, B, K, s, tid);
        else        cp_commit();
    }

    const int a_row  = (lane & 15);
    const int a_csel = (lane >> 4);
    const int b_rsel = ((lane >> 4) << 3) + (lane & 7);
    const int b_csel = ((lane >> 3) & 1);

    for (int kt = 0; kt < KT; kt++) {
        const int stage = kt % NST1;
        cp_wait<NST1 - 2>();
        __syncthreads();
        if (kt + NST1 - 1 < KT)
            load_stage128(sb, (kt + NST1 - 1) % NST1, A, B, K, kt + NST1 - 1, tid);
        else
            cp_commit();

        const unsigned ab = sb + stage * STAGE1;
        const unsigned bb = ab + 128 * 128;

        #pragma unroll
        for (int kk = 0; kk < 4; kk++) {
            const int c = kk * 2;
            unsigned af[2][4], bf[4][4];
            #pragma unroll
            for (int mi = 0; mi < 2; mi++) {
                int row = wm * 32 + mi * 16 + a_row;
                unsigned so = (unsigned)(row * 128 + (((c + a_csel) ^ (row & 7)) << 4));
                ldm4(af[mi][0], af[mi][1], af[mi][2], af[mi][3], ab + so);
            }
            #pragma unroll
            for (int nj2 = 0; nj2 < 4; nj2++) {
                int nrow = wn * 64 + nj2 * 16 + b_rsel;
                unsigned so = (unsigned)(nrow * 128 + (((c + b_csel) ^ (nrow & 7)) << 4));
                ldm4(bf[nj2][0], bf[nj2][1], bf[nj2][2], bf[nj2][3], bb + so);
            }
            #pragma unroll
            for (int mi = 0; mi < 2; mi++)
                #pragma unroll
                for (int nj = 0; nj < 8; nj++) {
                    const unsigned* b = bf[nj >> 1];
                    unsigned b0 = (nj & 1) ? b[2] : b[0];
                    unsigned b1 = (nj & 1) ? b[3] : b[1];
                    mma_f16(acc[mi][nj], af[mi][0], af[mi][1], af[mi][2], af[mi][3], b0, b1);
                }
        }
    }

    const int col0 = wn * 64 + (lane & 3) * 2;
    #pragma unroll
    for (int mi = 0; mi < 2; mi++) {
        int row = row_base + wm * 32 + mi * 16 + (lane >> 2);
        __half *p0 = nullptr, *p1 = nullptr;
        if (OUT_MODE == 2) {
            p0 = valp_row(C2, row) + col_base;
            p1 = valp_row(C2, row + 8) + col_base;
        }
        #pragma unroll
        for (int nj = 0; nj < 8; nj++) {
            int col = col0 + nj * 8;
            float b0v = bias[col], b1v = bias[col + 1];
            float v00 = acc[mi][nj][0] + b0v, v01 = acc[mi][nj][1] + b1v;
            float v10 = acc[mi][nj][2] + b0v, v11 = acc[mi][nj][3] + b1v;
            if (OUT_MODE == 0) {
                *(float2*)(Cf + (size_t)row * N + col)       = make_float2(v00, v01);
                *(float2*)(Cf + (size_t)(row + 8) * N + col) = make_float2(v10, v11);
            } else if (OUT_MODE == 1) {
                v00 = fmaxf(v00, 0.f); v01 = fmaxf(v01, 0.f);
                v10 = fmaxf(v10, 0.f); v11 = fmaxf(v11, 0.f);
                *(__half2*)(C2 + (size_t)row * N + col)       = __floats2half2_rn(v00, v01);
                *(__half2*)(C2 + (size_t)(row + 8) * N + col) = __floats2half2_rn(v10, v11);
            } else {
                *(__half2*)(p0 + col) = __floats2half2_rn(v00, v01);
                *(__half2*)(p1 + col) = __floats2half2_rn(v10, v11);
            }
        }
    }
}

// ffn1 GEMM: BM=128, relu + fp16 out
__global__ __launch_bounds__(256, 2)
void ffn1_gemm(const __half* __restrict__ A, const __half* __restrict__ Bt,
               const float* __restrict__ bias, __half* __restrict__ C2,
               int N, int K) {
    extern __shared__ __align__(1024) char smem[];
    const int bx = blockIdx.x, by = blockIdx.y;
    gemm_body128<1>(A + (size_t)by * 128 * K,
                    Bt + (size_t)bx * 128 * (size_t)K,
                    bias + bx * 128, nullptr, C2 + bx * 128,
                    N, K, by * 128, 0, smem);
}

// fused projection GEMM (BM=128): bx selects {off0, off1, logits, val0, val1}
__global__ __launch_bounds__(256, 2)
void proj_gemm(const __half* __restrict__ q1, const __half* __restrict__ src1,
               const __half* __restrict__ woffh, const __half* __restrict__ wattnh,
               const __half* __restrict__ wvalh,
               const float* __restrict__ b_off, const float* __restrict__ b_attn,
               const float* __restrict__ b_val,
               float* __restrict__ c_off, float* __restrict__ c_aw,
               __half* __restrict__ valp) {
    extern __shared__ __align__(1024) char smem[];
    const int bx = blockIdx.x, by = blockIdx.y;
    const int K = CCH;

    if (bx < 2) {
        gemm_body128<0>(q1 + (size_t)by * 128 * K, woffh + (size_t)bx * 128 * K,
                        b_off + bx * 128, c_off + bx * 128, nullptr,
                        CCH, K, by * 128, 0, smem);
    } else if (bx == 2) {
        gemm_body128<0>(q1 + (size_t)by * 128 * K, wattnh,
                        b_attn, c_aw, nullptr,
                        128, K, by * 128, 0, smem);
    } else {
        int s = bx - 3;
        gemm_body128<2>(src1 + (size_t)by * 128 * K, wvalh + (size_t)s * 128 * K,
                        b_val + s * 128, nullptr, valp,
                        CCH, K, by * 128, s * 128, smem);
    }
}

// ---------------------------------------------------------------------------
// Fused attn GEMM(BM=32, BN=256) + residual(src1 fp16) + LN1 -> x1 fp16.
// ---------------------------------------------------------------------------
#define ALN_STAGE ((32 + 256) * 128)        // 36864
#define ALN_CSTR 264
#define ALN_SMEM (2 * ALN_STAGE + 32 * ALN_CSTR * 4)   // 107520

__global__ __launch_bounds__(256, 2)
void attn_ln_gemm(const __half* __restrict__ A, const __half* __restrict__ Bt,
                  const float* __restrict__ bias, const __half* __restrict__ src1,
                  const float* __restrict__ g1, const float* __restrict__ be1,
                  __half* __restrict__ x1out) {
    extern __shared__ __align__(1024) char smem[];
    const unsigned sb = smem_u32(smem);
    float* cbuf = (float*)(smem + 2 * ALN_STAGE);
    const int tid = threadIdx.x;
    const int warp = tid >> 5, lane = tid & 31;
    const int row0 = blockIdx.x * 32;
    const int K = CCH;
    const int KT = 4;

    float acc[2][4][4];
    #pragma unroll
    for (int i = 0; i < 2; i++)
        #pragma unroll
        for (int j = 0; j < 4; j++)
            #pragma unroll
            for (int r = 0; r < 4; r++) acc[i][j][r] = 0.f;

    {
        const unsigned abase = sb;
        const unsigned bbase = sb + 32 * 128;
        const __half* ag = A + (size_t)row0 * K;
        {
            int r = tid >> 3, c = tid & 7;
            unsigned off = (unsigned)(r * 128 + ((c ^ (r & 7)) << 4));
            cp_async16(abase + off, ag + (size_t)r * K + c * 8);
        }
        #pragma unroll
        for (int i = 0; i < 8; i++) {
            int id = tid + i * 256;
            int r = id >> 3, c = id & 7;
            unsigned off = (unsigned)(r * 128 + ((c ^ (r & 7)) << 4));
            cp_async16(bbase + off, Bt + (size_t)r * K + c * 8);
        }
        cp_commit();
    }

    const int a_row  = (lane & 15);
    const int a_csel = (lane >> 4);
    const int b_rsel = ((lane >> 4) << 3) + (lane & 7);
    const int b_csel = ((lane >> 3) & 1);

    for (int kt = 0; kt < KT; kt++) {
        const int stage = kt & 1;
        cp_wait<0>();
        __syncthreads();
        if (kt + 1 < KT) {
            const unsigned abase = sb + (stage ^ 1) * ALN_STAGE;
            const unsigned bbase = abase + 32 * 128;
            const __half* ag = A + (size_t)row0 * K + (kt + 1) * 64;
            const __half* bg = Bt + (kt + 1) * 64;
            {
                int r = tid >> 3, c = tid & 7;
                unsigned off = (unsigned)(r * 128 + ((c ^ (r & 7)) << 4));
                cp_async16(abase + off, ag + (size_t)r * K + c * 8);
            }
            #pragma unroll
            for (int i = 0; i < 8; i++) {
                int id = tid + i * 256;
                int r = id >> 3, c = id & 7;
                unsigned off = (unsigned)(r * 128 + ((c ^ (r & 7)) << 4));
                cp_async16(bbase + off, bg + (size_t)r * K + c * 8);
            }
            cp_commit();
        }

        const unsigned ab = sb + stage * ALN_STAGE;
        const unsigned bb = ab + 32 * 128;

        #pragma unroll
        for (int kk = 0; kk < 4; kk++) {
            const int c = kk * 2;
            unsigned af[2][4], bf[2][4];
            #pragma unroll
            for (int mi = 0; mi < 2; mi++) {
                int row = mi * 16 + a_row;
                unsigned so = (unsigned)(row * 128 + (((c + a_csel) ^ (row & 7)) << 4));
                ldm4(af[mi][0], af[mi][1], af[mi][2], af[mi][3], ab + so);
            }
            #pragma unroll
            for (int nj2 = 0; nj2 < 2; nj2++) {
                int nrow = warp * 32 + nj2 * 16 + b_rsel;
                unsigned so = (unsigned)(nrow * 128 + (((c + b_csel) ^ (nrow & 7)) << 4));
                ldm4(bf[nj2][0], bf[nj2][1], bf[nj2][2], bf[nj2][3], bb + so);
            }
            #pragma unroll
            for (int mi = 0; mi < 2; mi++)
                #pragma unroll
                for (int nj = 0; nj < 4; nj++) {
                    const unsigned* b = bf[nj >> 1];
                    unsigned b0 = (nj & 1) ? b[2] : b[0];
                    unsigned b1 = (nj & 1) ? b[3] : b[1];
                    mma_f16(acc[mi][nj], af[mi][0], af[mi][1], af[mi][2], af[mi][3], b0, b1);
                }
        }
    }

    const int colw = warp * 32 + (lane & 3) * 2;
    #pragma unroll
    for (int mi = 0; mi < 2; mi++) {
        int r = mi * 16 + (lane >> 2);
        #pragma unroll
        for (int nj = 0; nj < 4; nj++) {
            int col = colw + nj * 8;
            float b0v = bias[col], b1v = bias[col + 1];
            cbuf[r * ALN_CSTR + col]           = acc[mi][nj][0] + b0v;
            cbuf[r * ALN_CSTR + col + 1]       = acc[mi][nj][1] + b1v;
            cbuf[(r + 8) * ALN_CSTR + col]     = acc[mi][nj][2] + b0v;
            cbuf[(r + 8) * ALN_CSTR + col + 1] = acc[mi][nj][3] + b1v;
        }
    }
    __syncthreads();

    #pragma unroll
    for (int rr = 0; rr < 4; rr++) {
        const int r = warp * 4 + rr;
        const size_t grow = (size_t)(row0 + r);
        const __half2* ps = (const __half2*)(src1 + grow * CCH);
        float v[8];
        float s = 0.f;
        #pragma unroll
        for (int j = 0; j < 4; j++) {
            int c2 = lane + 32 * j;                  // half2 index
            float2 sv = __half22float2(ps[c2]);
            v[2 * j]     = cbuf[r * ALN_CSTR + 2 * c2]     + sv.x;
            v[2 * j + 1] = cbuf[r * ALN_CSTR + 2 * c2 + 1] + sv.y;
            s += v[2 * j] + v[2 * j + 1];
        }
        #pragma unroll
        for (int o = 16; o > 0; o >>= 1) s += __shfl_xor_sync(0xffffffffu, s, o);
        const float mean = s * (1.f / CCH);
        float s2 = 0.f;
        #pragma unroll
        for (int j = 0; j < 8; j++) { float d = v[j] - mean; s2 += d * d; }
        #pragma unroll
        for (int o = 16; o > 0; o >>= 1) s2 += __shfl_xor_sync(0xffffffffu, s2, o);
        const float inv = rsqrtf(s2 * (1.f / CCH) + LN_EPS);
        #pragma unroll
        for (int j = 0; j < 4; j++) {
            int c = 2 * (lane + 32 * j);
            float y0 = (v[2 * j]     - mean) * inv * g1[c]     + be1[c];
            float y1 = (v[2 * j + 1] - mean) * inv * g1[c + 1] + be1[c + 1];
            *(__half2*)(x1out + grow * CCH + c) = __floats2half2_rn(y0, y1);
        }
    }
}

// ---------------------------------------------------------------------------
// merged prep: act conversion + border zero + weight transposes, one launch.
// ---------------------------------------------------------------------------
__global__ void prep_kernel(const float* __restrict__ src, const float* __restrict__ pos,
                            __half* __restrict__ q1, __half* __restrict__ s1,
                            __half* __restrict__ valp,
                            const float* __restrict__ w_off, const float* __restrict__ w_attn,
                            const float* __restrict__ w_val, const float* __restrict__ w_out,
                            const float* __restrict__ w1,    const float* __restrict__ w2,
                            __half* __restrict__ d_off, __half* __restrict__ d_attn,
                            __half* __restrict__ d_val, __half* __restrict__ d_out,
                            __half* __restrict__ d_w1,  __half* __restrict__ d_w2) {
    __shared__ float tile[32][33];
    const int bid = blockIdx.x;
    const int tid = threadIdx.x;

    if (bid < 10880) {
        int i = bid * 256 + tid;
        float2 s = ((const float2*)src)[i];
        float2 p = ((const float2*)pos)[i];
        ((__half2*)s1)[i] = __floats2half2_rn(s.x, s.y);
        ((__half2*)q1)[i] = __floats2half2_rn(s.x + p.x, s.y + p.y);
    } else if (bid < 14112) {
        const int gid = (bid - 10880) * 8 + (tid >> 5);
        const int lane = tid & 31;
        int cell = gid % PBATCH;
        int W4, loc;
        if (cell < PB1)      { loc = cell;       W4 = 68; }
        else if (cell < PB2) { loc = cell - PB1; W4 = 36; }
        else if (cell < PB3) { loc = cell - PB2; W4 = 20; }
        else                 { loc = cell - PB3; W4 = 12; }
        const int y = loc / W4, x = loc - y * W4;
        if ((y < 2) | (y >= W4 - 2) | (x < 2) | (x >= W4 - 2)) {
            uint4* p = (uint4*)(valp + (size_t)gid * CCH);
            p[lane] = make_uint4(0u, 0u, 0u, 0u);
        }
    } else {
        int id = bid - 14112;
        const float* W; __half* Bt; int K, N, nx, local;
        if      (id < 64)  { W = w_off;  Bt = d_off;  K = CCH; N = CCH; nx = 8;  local = id; }
        else if (id < 96)  { W = w_attn; Bt = d_attn; K = CCH; N = 128; nx = 4;  local = id - 64; }
        else if (id < 160) { W = w_val;  Bt = d_val;  K = CCH; N = CCH; nx = 8;  local = id - 96; }
        else if (id < 224) { W = w_out;  Bt = d_out;  K = CCH; N = CCH; nx = 8;  local = id - 160; }
        else if (id < 480) { W = w1;     Bt = d_w1;   K = CCH; N = DFF; nx = 32; local = id - 224; }
        else               { W = w2;     Bt = d_w2;   K = DFF; N = CCH; nx = 8;  local = id - 480; }
        const int n0 = (local % nx) * 32, k0 = (local / nx) * 32;
        const int tx = tid & 31, ty = tid >> 5;
        #pragma unroll
        for (int i = 0; i < 4; i++) {
            int k = ty + i * 8;
            tile[k][tx] = W[(size_t)(k0 + k) * N + n0 + tx];
        }
        __syncthreads();
        #pragma unroll
        for (int i = 0; i < 4; i++) {
            int n = ty + i * 8;
            Bt[(size_t)(n0 + n) * K + k0 + tx] = __float2half_rn(tile[tx][n]);
        }
    }
}

// ---------------------------------------------------------------------------
// MSDA: half2 channels, one warp serves two heads. 512 threads = 4 tokens.
// ---------------------------------------------------------------------------
__global__ __launch_bounds__(512)
void msda_kernel(const __half* __restrict__ valp,
                 const float* __restrict__ off,
                 const float* __restrict__ logits,
                 const float* __restrict__ refp,
                 __half* __restrict__ out1) {
    const int warp = threadIdx.x >> 5;
    const int lane = threadIdx.x & 31;
    const int hp = warp & 3;
    const int t  = blockIdx.x * 4 + (warp >> 2);
    const int b  = t / LEN;
    const int p  = lane & 15;
    const int h  = hp * 2 + (lane >> 4);
    const int hsel = lane & 16;

    const float* lg = logits + (size_t)t * 128 + h * 16;
    float l0 = lg[p];
    float mx = l0;
    #pragma unroll
    for (int o = 1; o < 16; o <<= 1) mx = fmaxf(mx, __shfl_xor_sync(0xffffffffu, mx, o));
    float e = __expf(l0 - mx);
    float s = e;
    #pragma unroll
    for (int o = 1; o < 16; o <<= 1) s += __shfl_xor_sync(0xffffffffu, s, o);
    const float wgt = e / s;

    const int l  = p >> 2;
    const int Wl = 64 >> l;
    const int W4 = Wl + 4;
    const int base = (l == 0) ? PB0 : (l == 1) ? PB1 : (l == 2) ? PB2 : PB3;
    const float2* off2 = (const float2*)(off + (size_t)t * CCH + h * (NL * NP * 2));
    const float2* ref2 = (const float2*)(refp + (size_t)t * (NL * 2));
    float2 o2 = off2[p];
    float2 r2 = ref2[l];
    const float fW = (float)Wl;
    const float px = fmaf(r2.x, fW, o2.x - 0.5f);
    const float py = fmaf(r2.y, fW, o2.y - 0.5f);
    const float fx = floorf(px), fy = floorf(py);
    const int x0 = (int)fx, y0 = (int)fy;
    const float wx1 = px - fx, wy1 = py - fy;
    const float wx0 = 1.f - wx1, wy0 = 1.f - wy1;
    const int x0c = min(max(x0, -2), Wl);
    const int y0c = min(max(y0, -2), Wl);
    const int rcell = base + (y0c + 2) * W4 + (x0c + 2);
    const float w00 = wgt * wx0 * wy0;
    const float w10 = wgt * wx1 * wy0;
    const float w01 = wgt * wx0 * wy1;
    const float w11 = wgt * wx1 * wy1;

    const __half* vbase = valp + ((size_t)b * PBATCH) * CCH + h * DH + p * 2;
    float accx = 0.f, accy = 0.f;

    #pragma unroll
    for (int q = 0; q < 16; q++) {
        const int W4q = (64 >> (q >> 2)) + 4;
        const int src = q | hsel;
        const int rc  = __shfl_sync(0xffffffffu, rcell, src);
        const float a00 = __shfl_sync(0xffffffffu, w00, src);
        const float a10 = __shfl_sync(0xffffffffu, w10, src);
        const float a01 = __shfl_sync(0xffffffffu, w01, src);
        const float a11 = __shfl_sync(0xffffffffu, w11, src);
        const __half* qp = vbase + (size_t)rc * CCH;
        float2 v00 = __half22float2(*(const __half2*)(qp));
        float2 v10 = __half22float2(*(const __half2*)(qp + CCH));
        float2 v01 = __half22float2(*(const __half2*)(qp + (size_t)W4q * CCH));
        float2 v11 = __half22float2(*(const __half2*)(qp + (size_t)(W4q + 1) * CCH));
        accx = fmaf(a00, v00.x, accx); accy = fmaf(a00, v00.y, accy);
        accx = fmaf(a10, v10.x, accx); accy = fmaf(a10, v10.y, accy);
        accx = fmaf(a01, v01.x, accx); accy = fmaf(a01, v01.y, accy);
        accx = fmaf(a11, v11.x, accx); accy = fmaf(a11, v11.y, accy);
    }
    *(__half2*)(out1 + (size_t)t * CCH + h * DH + p * 2) = __floats2half2_rn(accx, accy);
}

// ---------------------------------------------------------------------------
// Final LN2: out = LN(x1 + ffn), fp16 inputs, 512 threads = 16 rows/CTA.
// ---------------------------------------------------------------------------
__global__ __launch_bounds__(512)
void ln2_kernel(const __half* __restrict__ a, const __half* __restrict__ b,
                const float* __restrict__ g, const float* __restrict__ be,
                float* __restrict__ out, int rows) {
    const int row = blockIdx.x * 16 + (threadIdx.x >> 5);
    const int lane = threadIdx.x & 31;
    if (row >= rows) return;

    const __half2* pa = (const __half2*)(a + (size_t)row * CCH);
    const __half2* pb = (const __half2*)(b + (size_t)row * CCH);
    float2 v[4];
    float s = 0.f;
    #pragma unroll
    for (int j = 0; j < 4; j++) {
        int c = lane + 32 * j;
        float2 va = __half22float2(pa[c]);
        float2 vb = __half22float2(pb[c]);
        v[j].x = va.x + vb.x;
        v[j].y = va.y + vb.y;
        s += v[j].x + v[j].y;
    }
    #pragma unroll
    for (int o = 16; o > 0; o >>= 1) s += __shfl_xor_sync(0xffffffffu, s, o);
    const float mean = s * (1.f / CCH);
    float s2 = 0.f;
    #pragma unroll
    for (int j = 0; j < 4; j++) {
        float dx = v[j].x - mean, dy = v[j].y - mean;
        s2 += dx * dx + dy * dy;
    }
    #pragma unroll
    for (int o = 16; o > 0; o >>= 1) s2 += __shfl_xor_sync(0xffffffffu, s2, o);
    const float inv = rsqrtf(s2 * (1.f / CCH) + LN_EPS);

    float* po = out + (size_t)row * CCH;
    #pragma unroll
    for (int j = 0; j < 4; j++) {
        int c = lane + 32 * j;
        float y0 = (v[j].x - mean) * inv * g[2 * c]     + be[2 * c];
        float y1 = (v[j].y - mean) * inv * g[2 * c + 1] + be[2 * c + 1];
        *(float2*)(po + 2 * c) = make_float2(y0, y1);
    }
}

// ---------------------------------------------------------------------------
// launch
// ---------------------------------------------------------------------------
extern "C" void kernel_launch(void* const* d_in, const int* in_sizes, int n_in,
                              void* d_out, int out_size) {
    const float* src   = (const float*)d_in[0];
    const float* pos   = (const float*)d_in[1];
    const float* refp  = (const float*)d_in[2];
    const float* w_off  = (const float*)d_in[6];
    const float* b_off  = (const float*)d_in[7];
    const float* w_attn = (const float*)d_in[8];
    const float* b_attn = (const float*)d_in[9];
    const float* w_val  = (const float*)d_in[10];
    const float* b_val  = (const float*)d_in[11];
    const float* w_out  = (const float*)d_in[12];
    const float* b_out  = (const float*)d_in[13];
    const float* g1     = (const float*)d_in[14];
    const float* be1    = (const float*)d_in[15];
    const float* w1     = (const float*)d_in[16];
    const float* b1     = (const float*)d_in[17];
    const float* w2     = (const float*)d_in[18];
    const float* b2     = (const float*)d_in[19];
    const float* g2     = (const float*)d_in[20];
    const float* be2    = (const float*)d_in[21];
    float* out = (float*)d_out;

    __half *p_q1, *p_src1, *p_msda1, *p_x1, *p_h1, *p_valp;
    __half *p_woffh, *p_wattnh, *p_wvalh, *p_wouth, *p_w1h, *p_w2h;
    float *p_off, *p_aw;
    cudaGetSymbolAddress((void**)&p_q1,    g_q1);
    cudaGetSymbolAddress((void**)&p_src1,  g_src1);
    cudaGetSymbolAddress((void**)&p_msda1, g_msda1);
    cudaGetSymbolAddress((void**)&p_x1,    g_x1);
    cudaGetSymbolAddress((void**)&p_h1,    g_h1);
    cudaGetSymbolAddress((void**)&p_valp,  g_valp);
    cudaGetSymbolAddress((void**)&p_woffh, g_woffh);
    cudaGetSymbolAddress((void**)&p_wattnh,g_wattnh);
    cudaGetSymbolAddress((void**)&p_wvalh, g_wvalh);
    cudaGetSymbolAddress((void**)&p_wouth, g_wouth);
    cudaGetSymbolAddress((void**)&p_w1h,   g_w1h);
    cudaGetSymbolAddress((void**)&p_w2h,   g_w2h);
    cudaGetSymbolAddress((void**)&p_off,   g_off);
    cudaGetSymbolAddress((void**)&p_aw,    g_aw);

    const int M = NTOK;  // 21760 = 170 * 128 = 340 * 64 = 680 * 32
    const dim3 blk(256);

    const int SM_A = NST  * STAGE_SZ;   // 98304
    const int SM_B = NST1 * STAGE1;     // 98304
    cudaFuncSetAttribute(proj_gemm,    cudaFuncAttributeMaxDynamicSharedMemorySize, SM_B);
    cudaFuncSetAttribute(ffn1_gemm,    cudaFuncAttributeMaxDynamicSharedMemorySize, SM_B);
    cudaFuncSetAttribute(mma_gemm64,   cudaFuncAttributeMaxDynamicSharedMemorySize, SM_A);
    cudaFuncSetAttribute(attn_ln_gemm, cudaFuncAttributeMaxDynamicSharedMemorySize, ALN_SMEM);

    // merged prep: act conversion + border zero + weight transposes
    prep_kernel<<<14848, blk>>>(src, pos, p_q1, p_src1, p_valp,
                                w_off, w_attn, w_val, w_out, w1, w2,
                                p_woffh, p_wattnh, p_wvalh, p_wouth, p_w1h, p_w2h);

    // fused projections (BM=128): off / logits / value(padded fp16)
    proj_gemm<<<dim3(5, M / 128), blk, SM_B>>>(p_q1, p_src1, p_woffh, p_wattnh, p_wvalh,
                                               b_off, b_attn, b_val, p_off, p_aw, p_valp);
    // MSDA gather (softmax fused, half2 channels, 2 heads per warp, 4 tok/CTA)
    msda_kernel<<<NTOK / 4, 512>>>(p_valp, p_off, p_aw, refp, p_msda1);
    // attn_out GEMM + residual(src1 fp16) + LN1 -> x1 fp16
    attn_ln_gemm<<<M / 32, blk, ALN_SMEM>>>(p_msda1, p_wouth, b_out, p_src1, g1, be1, p_x1);
    // h = relu(x1 @ w1 + b1) -> fp16 (BM=128)
    ffn1_gemm<<<dim3(8, M / 128), blk, SM_B>>>(p_x1, p_w1h, b1, p_h1, DFF, CCH);
    // ffn = h @ w2 + b2 -> fp16 (reuse msda buffer)
    mma_gemm64<<<dim3(2, M / 64), blk, SM_A>>>(p_h1, p_w2h, b2, p_msda1, CCH, DFF);
    // out = LN(x1 + ffn), fp16 inputs
    ln2_kernel<<<(NTOK + 15) / 16, 512>>>(p_x1, p_msda1, g2, be2, out, NTOK);
}